// round 9
// baseline (speedup 1.0000x reference)
#include <cuda_runtime.h>
#include <cuda_fp16.h>
#include <mma.h>
#include <math.h>
#include <stdint.h>

using namespace nvcuda;

#define BATCH 2
#define SEQ   2048
#define HID   4096
#define NHEAD 32
#define HDIM  128
#define MROWS (BATCH*SEQ)     /* 4096 */
#define QKVN  (3*HID)         /* 12288 */

// ---------------- scratch ----------------
__device__ int8_t g_Xh8 [MROWS*HID];
__device__ int8_t g_Xl8 [MROWS*HID];
__device__ int8_t g_Wqh8[QKVN*HID];
__device__ int8_t g_Wql8[QKVN*HID];
__device__ float  g_sX  [MROWS];
__device__ float  g_sW  [QKVN];
__device__ __half g_Wohi[HID*HID];
__device__ __half g_Wolo[HID*HID];
__device__ __half g_Qhi [MROWS*HID];
__device__ __half g_Qlo [MROWS*HID];
__device__ __half g_Khi [MROWS*HID];
__device__ __half g_Klo [MROWS*HID];
__device__ __half g_V   [MROWS*HID];
__device__ __half g_AOhi[MROWS*HID];
__device__ __half g_AOlo[MROWS*HID];
__device__ float  g_cos [SEQ*64];
__device__ float  g_sin [SEQ*64];

__device__ __forceinline__ void splitf(float x, __half &hi, __half &lo) {
    hi = __float2half(x);
    lo = __float2half(x - __half2float(hi));
}

// ---------------- cp.async helpers ----------------
static __device__ __forceinline__ uint32_t smem_u32(const void* p) {
    uint32_t a;
    asm("{ .reg .u64 t; cvta.to.shared.u64 t, %1; cvt.u32.u64 %0, t; }" : "=r"(a) : "l"(p));
    return a;
}
static __device__ __forceinline__ void cp_async16(uint32_t dst, const void* src) {
    asm volatile("cp.async.cg.shared.global [%0], [%1], 16;\n" :: "r"(dst), "l"(src));
}
#define CP_COMMIT() asm volatile("cp.async.commit_group;\n" ::: "memory")
#define CP_WAIT1()  asm volatile("cp.async.wait_group 1;\n" ::: "memory")

// ---------------- quantize rows to 2 int8 limbs: x = s*(h + l/256) ----------------
__global__ void __launch_bounds__(256) quant_rows_kernel(
    const float* __restrict__ src, int8_t* __restrict__ h8, int8_t* __restrict__ l8,
    float* __restrict__ scale, int K)
{
    int row = blockIdx.x;
    int tid = threadIdx.x;
    const float* x = src + (size_t)row * K;
    __shared__ float red[256];
    float m = 0.0f;
    for (int i = tid; i < K; i += 256) m = fmaxf(m, fabsf(x[i]));
    red[tid] = m; __syncthreads();
    for (int s = 128; s > 0; s >>= 1) {
        if (tid < s) red[tid] = fmaxf(red[tid], red[tid + s]);
        __syncthreads();
    }
    float s = fmaxf(red[0] * (1.0f / 127.0f), 1e-30f);
    float inv = 1.0f / s;
    if (tid == 0) scale[row] = s;
    for (int i = tid; i < K; i += 256) {
        float v = x[i];
        int h = __float2int_rn(v * inv);
        h = max(-127, min(127, h));
        float r = v - s * (float)h;
        int l = __float2int_rn(r * inv * 256.0f);
        l = max(-127, min(127, l));
        h8[(size_t)row * K + i] = (int8_t)h;
        l8[(size_t)row * K + i] = (int8_t)l;
    }
}

// ---------------- fp16 split kernel (W_o only) ----------------
__global__ void __launch_bounds__(256) split_wo_kernel(const float* __restrict__ src) {
    int idx = blockIdx.x * blockDim.x + threadIdx.x;
    if (idx < HID*HID) {
        float x = src[idx];
        __half h, l; splitf(x, h, l);
        g_Wohi[idx] = h; g_Wolo[idx] = l;
    }
}

// ---------------- RoPE cos/sin table ----------------
__global__ void __launch_bounds__(256) rope_table_kernel() {
    int idx = blockIdx.x * blockDim.x + threadIdx.x;
    if (idx >= SEQ*64) return;
    int i = idx & 63;
    int s = idx >> 6;
    double inv = pow(10000.0, -((double)(2*i)) / 128.0);
    float invf = (float)inv;
    float ang  = (float)s * invf;
    g_cos[idx] = (float)cos((double)ang);
    g_sin[idx] = (float)sin((double)ang);
}

// =====================================================================
//  int8 limb-split QKV GEMM: CTA 128x128, 512 threads, warp 32x32.
//  KC=64, 2-stage cp.async. 3 IMMA terms: h·h -> acc_hh ; h·l + l·h -> acc_m.
//  C = sX[row]*sW[col]*(hh + m/256). Fused RoPE (Q/K) / fp16 V epilogue.
// =====================================================================

#define KCI       64
#define IARR      (128*80)                  /* 64 data bytes + 16 pad per row */
#define ISTAGE    (4*IARR)                  /* 40960 */
#define IGEMM_SMEM (2*ISTAGE)               /* 81920 */

static __device__ __forceinline__ void qkv_load_stage(
    uint32_t stage_base, int tid, int bm, int bn, int k0)
{
    int chunk = tid & 3;        // 16B chunk within 64B data row
    int r0    = tid >> 2;       // 0..127
    const char* gAh = (const char*)g_Xh8  + (size_t)(bm + r0) * HID + k0 + chunk * 16;
    const char* gAl = (const char*)g_Xl8  + (size_t)(bm + r0) * HID + k0 + chunk * 16;
    const char* gBh = (const char*)g_Wqh8 + (size_t)(bn + r0) * HID + k0 + chunk * 16;
    const char* gBl = (const char*)g_Wql8 + (size_t)(bn + r0) * HID + k0 + chunk * 16;
    uint32_t so = (uint32_t)(r0 * 80 + chunk * 16);
    cp_async16(stage_base + so,          gAh);
    cp_async16(stage_base + IARR + so,   gAl);
    cp_async16(stage_base + 2*IARR + so, gBh);
    cp_async16(stage_base + 3*IARR + so, gBl);
}

__global__ void __launch_bounds__(512, 1) gemm_qkv_i8_kernel(int grid_m, int grid_n)
{
    extern __shared__ signed char smi[];
    uint32_t smem_base = smem_u32(smi);
    int tid = threadIdx.x;
    int wid = tid >> 5;

    int pid = blockIdx.x;
    const int GRPW = 8;
    int width = GRPW * grid_n;
    int g   = pid / width;
    int rem = pid - g * width;
    int gm  = grid_m - g * GRPW; if (gm > GRPW) gm = GRPW;
    int bm  = (g * GRPW + (rem % gm)) * 128;
    int bn  = (rem / gm) * 128;

    int wm = (wid >> 2) * 32;   // 4 warp rows of 32
    int wn = (wid & 3) * 32;    // 4 warp cols of 32

    wmma::fragment<wmma::accumulator,16,16,16,int> hh[2][2], mx[2][2];
    #pragma unroll
    for (int i = 0; i < 2; i++)
        #pragma unroll
        for (int j = 0; j < 2; j++) {
            wmma::fill_fragment(hh[i][j], 0);
            wmma::fill_fragment(mx[i][j], 0);
        }

    const int NIT = HID / KCI;   // 64

    qkv_load_stage(smem_base,          tid, bm, bn, 0);
    CP_COMMIT();
    qkv_load_stage(smem_base + ISTAGE, tid, bm, bn, KCI);
    CP_COMMIT();

    for (int it = 0; it < NIT; it++) {
        CP_WAIT1();
        __syncthreads();

        const signed char* st  = smi + (size_t)(it & 1) * ISTAGE;
        const signed char* sAh = st;
        const signed char* sAl = st + IARR;
        const signed char* sBh = st + 2*IARR;
        const signed char* sBl = st + 3*IARR;

        #pragma unroll
        for (int kk = 0; kk < 4; kk++) {
            wmma::fragment<wmma::matrix_b,16,16,16,signed char,wmma::col_major> bh[2], bl[2];
            #pragma unroll
            for (int j = 0; j < 2; j++) {
                wmma::load_matrix_sync(bh[j], sBh + (wn + j*16)*80 + kk*16, 80);
                wmma::load_matrix_sync(bl[j], sBl + (wn + j*16)*80 + kk*16, 80);
            }
            #pragma unroll
            for (int i = 0; i < 2; i++) {
                wmma::fragment<wmma::matrix_a,16,16,16,signed char,wmma::row_major> ah, al;
                wmma::load_matrix_sync(ah, sAh + (wm + i*16)*80 + kk*16, 80);
                wmma::load_matrix_sync(al, sAl + (wm + i*16)*80 + kk*16, 80);
                #pragma unroll
                for (int j = 0; j < 2; j++) {
                    wmma::mma_sync(hh[i][j], ah, bh[j], hh[i][j]);
                    wmma::mma_sync(mx[i][j], ah, bl[j], mx[i][j]);
                    wmma::mma_sync(mx[i][j], al, bh[j], mx[i][j]);
                }
            }
        }
        __syncthreads();

        int nxt = it + 2;
        if (nxt < NIT)
            qkv_load_stage(smem_base + (uint32_t)(nxt & 1) * ISTAGE, tid, bm, bn, nxt * KCI);
        CP_COMMIT();
    }

    // combine limbs in registers, stage to smem as float
    float* sC = (float*)smi;     // 128 x 132
    #pragma unroll
    for (int i = 0; i < 2; i++)
        #pragma unroll
        for (int j = 0; j < 2; j++) {
            wmma::fragment<wmma::accumulator,16,16,16,float> f;
            #pragma unroll
            for (int e = 0; e < f.num_elements; e++)
                f.x[e] = (float)hh[i][j].x[e] + (float)mx[i][j].x[e] * 0.00390625f;
            wmma::store_matrix_sync(sC + (wm + i*16)*132 + wn + j*16, f,
                                    132, wmma::mem_row_major);
        }
    __syncthreads();

    int h = (bn >> 7) & 31;
    if (bn < 2*HID) {
        // Q/K: RoPE + transpose + hi/lo split
        bool isk = (bn >= HID);
        __half* Dh = isk ? g_Khi : g_Qhi;
        __half* Dl = isk ? g_Klo : g_Qlo;
        for (int idx = tid; idx < 128*64; idx += 512) {
            int r = idx >> 6, d = idx & 63;
            float sa = g_sX[bm + r];
            float x1 = sC[r*132 + d]      * sa * g_sW[bn + d];
            float x2 = sC[r*132 + d + 64] * sa * g_sW[bn + d + 64];
            int row = bm + r;
            int s   = row & (SEQ-1);
            int b   = row >> 11;
            float c  = g_cos[s*64 + d];
            float sn = g_sin[s*64 + d];
            float o1 = x1*c - x2*sn;
            float o2 = x1*sn + x2*c;
            size_t dst = (((size_t)b * NHEAD + h) * SEQ + s) * HDIM + d;
            __half hi, lo;
            splitf(o1, hi, lo); Dh[dst]    = hi; Dl[dst]    = lo;
            splitf(o2, hi, lo); Dh[dst+64] = hi; Dl[dst+64] = lo;
        }
    } else {
        // V: fp16 transpose
        for (int idx = tid; idx < 128*128; idx += 512) {
            int r = idx >> 7, d = idx & 127;
            float v = sC[r*132 + d] * g_sX[bm + r] * g_sW[bn + d];
            int row = bm + r;
            int s   = row & (SEQ-1);
            int b   = row >> 11;
            g_V[(((size_t)b * NHEAD + h) * SEQ + s) * HDIM + d] = __float2half(v);
        }
    }
}

// =====================================================================
//  fp16 2-term out projection (unchanged R7 config): CTA 128x128, 256 thr.
// =====================================================================

#define KC        32
#define ARR_HALF  (128*40)
#define STAGE_HALF (4*ARR_HALF)
#define STAGE_BYTES (STAGE_HALF*2)
#define GEMM_SMEM (2*STAGE_BYTES)          /* 81920 */

static __device__ __forceinline__ void out_load_stage(
    uint32_t stage_base, int tid,
    const __half* __restrict__ Ahi, const __half* __restrict__ Alo,
    const __half* __restrict__ Bhi, const __half* __restrict__ Blo,
    int bm, int bn, int K, int k0)
{
    int chunk = tid & 3;
    int r0    = tid >> 2;
    const char* gAh = (const char*)(Ahi + (size_t)bm * K + k0) + chunk * 16;
    const char* gAl = (const char*)(Alo + (size_t)bm * K + k0) + chunk * 16;
    const char* gBh = (const char*)(Bhi + (size_t)bn * K + k0) + chunk * 16;
    const char* gBl = (const char*)(Blo + (size_t)bn * K + k0) + chunk * 16;
    #pragma unroll
    for (int u = 0; u < 2; u++) {
        int row = r0 + u * 64;
        uint32_t so = (uint32_t)(row * 80 + chunk * 16);
        cp_async16(stage_base + so,                 gAh + (size_t)row * K * 2);
        cp_async16(stage_base + 2*ARR_HALF + so,    gAl + (size_t)row * K * 2);
        cp_async16(stage_base + 4*ARR_HALF + so,    gBh + (size_t)row * K * 2);
        cp_async16(stage_base + 6*ARR_HALF + so,    gBl + (size_t)row * K * 2);
    }
}

__global__ void __launch_bounds__(256, 2) gemm_out_kernel(
    const __half* __restrict__ Ahi, const __half* __restrict__ Alo,
    const __half* __restrict__ Bhi, const __half* __restrict__ Blo,
    float* __restrict__ C, int K, int ldc, int grid_m, int grid_n)
{
    extern __shared__ __half smh[];
    uint32_t smem_base = smem_u32(smh);
    int tid = threadIdx.x;
    int wid = tid >> 5;

    int pid = blockIdx.x;
    const int GRPW = 16;
    int width = GRPW * grid_n;
    int g   = pid / width;
    int rem = pid - g * width;
    int gm  = grid_m - g * GRPW; if (gm > GRPW) gm = GRPW;
    int bm  = (g * GRPW + (rem % gm)) * 128;
    int bn  = (rem / gm) * 128;

    int wm = (wid >> 2) * 64;
    int wn = (wid & 3) * 32;

    wmma::fragment<wmma::accumulator,16,16,16,float> acc[4][2];
    #pragma unroll
    for (int i = 0; i < 4; i++)
        #pragma unroll
        for (int j = 0; j < 2; j++)
            wmma::fill_fragment(acc[i][j], 0.0f);

    const int NIT = K / KC;

    out_load_stage(smem_base,               tid, Ahi, Alo, Bhi, Blo, bm, bn, K, 0);
    CP_COMMIT();
    out_load_stage(smem_base + STAGE_BYTES, tid, Ahi, Alo, Bhi, Blo, bm, bn, K, KC);
    CP_COMMIT();

    for (int it = 0; it < NIT; it++) {
        CP_WAIT1();
        __syncthreads();

        const __half* st  = smh + (size_t)(it & 1) * STAGE_HALF;
        const __half* sAh = st;
        const __half* sAl = st + ARR_HALF;
        const __half* sBh = st + 2*ARR_HALF;
        const __half* sBl = st + 3*ARR_HALF;

        #pragma unroll
        for (int kk = 0; kk < 2; kk++) {
            wmma::fragment<wmma::matrix_b,16,16,16,__half,wmma::col_major> bh[2], bl[2];
            #pragma unroll
            for (int j = 0; j < 2; j++) {
                wmma::load_matrix_sync(bh[j], sBh + (wn + j*16)*40 + kk*16, 40);
                wmma::load_matrix_sync(bl[j], sBl + (wn + j*16)*40 + kk*16, 40);
            }
            #pragma unroll
            for (int i = 0; i < 4; i++) {
                wmma::fragment<wmma::matrix_a,16,16,16,__half,wmma::row_major> ah;
                wmma::load_matrix_sync(ah, sAh + (wm + i*16)*40 + kk*16, 40);
                #pragma unroll
                for (int j = 0; j < 2; j++) {
                    wmma::mma_sync(acc[i][j], ah, bh[j], acc[i][j]);
                    wmma::mma_sync(acc[i][j], ah, bl[j], acc[i][j]);
                }
            }
        }
        __syncthreads();

        int nxt = it + 2;
        if (nxt < NIT)
            out_load_stage(smem_base + (uint32_t)(nxt & 1) * STAGE_BYTES, tid,
                           Ahi, Alo, Bhi, Blo, bm, bn, K, nxt * KC);
        CP_COMMIT();
    }

    #pragma unroll
    for (int i = 0; i < 4; i++)
        #pragma unroll
        for (int j = 0; j < 2; j++) {
            size_t off = (size_t)(bm + wm + i*16) * ldc + bn + wn + j*16;
            wmma::store_matrix_sync(&C[off], acc[i][j], ldc, wmma::mem_row_major);
        }
}

// ---------------- flash attention (unchanged) ----------------
#define TILE_H   (64*136)
#define TILE_B   (TILE_H*2)
#define FL_SMEM  (8*TILE_B + 64*68*4 + 64*72*2 + 64*132*4 + 3*64*4)

static __device__ __forceinline__ void flash_issue_tile(
    uint32_t dKh, uint32_t dKl, uint32_t dV,
    const __half* __restrict__ Kh, const __half* __restrict__ Kl,
    const __half* __restrict__ V, int tid)
{
    int chunk = tid & 15;
    int r0    = tid >> 4;
    #pragma unroll
    for (int u = 0; u < 4; u++) {
        int r = r0 + u * 16;
        uint32_t so = (uint32_t)(r * 272 + chunk * 16);
        size_t   go = (size_t)r * HDIM * 2 + chunk * 16;
        cp_async16(dKh + so, (const char*)Kh + go);
        cp_async16(dKl + so, (const char*)Kl + go);
        cp_async16(dV  + so, (const char*)V  + go);
    }
}

__global__ void __launch_bounds__(256) flash_kernel() {
    extern __shared__ unsigned char smraw[];
    __half* sQh = (__half*)smraw;
    __half* sQl = sQh + TILE_H;
    __half* sKB = sQl + TILE_H;
    float*  sS  = (float*)(sKB + 6*TILE_H);
    __half* sP  = (__half*)(sS + 64*68);
    float*  sO  = (float*)(sP + 64*72);
    float*  smx = sO + 64*132;
    float*  sl  = smx + 64;

    int tid = threadIdx.x;
    int wid = tid >> 5;
    int qt  = gridDim.x - 1 - blockIdx.x;
    int h   = blockIdx.y;
    int b   = blockIdx.z;
    int bh  = b * NHEAD + h;
    int q0  = qt * 64;

    const float scale = 0.08838834764831845f;

    const __half* Khg = g_Khi + (size_t)bh * SEQ * HDIM;
    const __half* Klg = g_Klo + (size_t)bh * SEQ * HDIM;
    const __half* Vg  = g_V   + (size_t)bh * SEQ * HDIM;

    uint32_t sKB_u = smem_u32(sKB);

    flash_issue_tile(sKB_u, sKB_u + TILE_B, sKB_u + 2*TILE_B, Khg, Klg, Vg, tid);
    CP_COMMIT();

    {
        const __half* Qh = g_Qhi + ((size_t)bh * SEQ + q0) * HDIM;
        const __half* Ql = g_Qlo + ((size_t)bh * SEQ + q0) * HDIM;
        for (int v = tid; v < 1024; v += 256) {
            int r = v >> 4, c = (v & 15) << 3;
            *(int4*)(sQh + r*136 + c) = *(const int4*)(Qh + r*HDIM + c);
            *(int4*)(sQl + r*136 + c) = *(const int4*)(Ql + r*HDIM + c);
        }
    }
    for (int v = tid; v < 64*132; v += 256) sO[v] = 0.0f;
    if (tid < 64) { smx[tid] = -INFINITY; sl[tid] = 0.0f; }

    int wm = (wid >> 1) * 16;

    for (int kt = 0; kt <= qt; kt++) {
        if (kt + 1 <= qt) {
            uint32_t nb = sKB_u + (uint32_t)((kt + 1) & 1) * 3 * TILE_B;
            flash_issue_tile(nb, nb + TILE_B, nb + 2*TILE_B,
                             Khg + (size_t)(kt+1)*64*HDIM,
                             Klg + (size_t)(kt+1)*64*HDIM,
                             Vg  + (size_t)(kt+1)*64*HDIM, tid);
        }
        CP_COMMIT();
        CP_WAIT1();
        __syncthreads();

        __half* sKh = sKB + (size_t)(kt & 1) * 3 * TILE_H;
        __half* sKl = sKh + TILE_H;
        __half* sV  = sKh + 2*TILE_H;

        {
            int wn = (wid & 1) * 32;
            wmma::fragment<wmma::accumulator,16,16,16,float> sacc[2];
            wmma::fill_fragment(sacc[0], 0.0f);
            wmma::fill_fragment(sacc[1], 0.0f);
            #pragma unroll
            for (int d8 = 0; d8 < 8; d8++) {
                wmma::fragment<wmma::matrix_a,16,16,16,__half,wmma::row_major> ah, al;
                wmma::load_matrix_sync(ah, sQh + wm*136 + d8*16, 136);
                wmma::load_matrix_sync(al, sQl + wm*136 + d8*16, 136);
                #pragma unroll
                for (int j = 0; j < 2; j++) {
                    wmma::fragment<wmma::matrix_b,16,16,16,__half,wmma::col_major> kh, kl;
                    wmma::load_matrix_sync(kh, sKh + (wn + j*16)*136 + d8*16, 136);
                    wmma::load_matrix_sync(kl, sKl + (wn + j*16)*136 + d8*16, 136);
                    wmma::mma_sync(sacc[j], ah, kh, sacc[j]);
                    wmma::mma_sync(sacc[j], ah, kl, sacc[j]);
                    wmma::mma_sync(sacc[j], al, kh, sacc[j]);
                }
            }
            wmma::store_matrix_sync(sS + wm*68 + wn,      sacc[0], 68, wmma::mem_row_major);
            wmma::store_matrix_sync(sS + wm*68 + wn + 16, sacc[1], 68, wmma::mem_row_major);
        }
        __syncthreads();

        {
            int r    = tid >> 2;
            int lane = tid & 3;
            bool diag = (kt == qt);
            int jmax = diag ? (r + 1) : 64;

            float lm = -INFINITY;
            #pragma unroll
            for (int jj = 0; jj < 16; jj++) {
                int j = lane*16 + jj;
                if (j < jmax) lm = fmaxf(lm, sS[r*68 + j] * scale);
            }
            lm = fmaxf(lm, __shfl_xor_sync(0xffffffffu, lm, 1));
            lm = fmaxf(lm, __shfl_xor_sync(0xffffffffu, lm, 2));
            float mo = smx[r];
            float mn = fmaxf(mo, lm);

            float rl = 0.0f;
            #pragma unroll
            for (int jj = 0; jj < 16; jj++) {
                int j = lane*16 + jj;
                float p = 0.0f;
                if (j < jmax) { p = __expf(sS[r*68 + j] * scale - mn); rl += p; }
                sP[r*72 + j] = __float2half(p);
            }
            rl += __shfl_xor_sync(0xffffffffu, rl, 1);
            rl += __shfl_xor_sync(0xffffffffu, rl, 2);

            float a = __expf(mo - mn);
            if (lane == 0) {
                smx[r] = mn;
                sl[r]  = sl[r] * a + rl;
            }
            #pragma unroll
            for (int dd = 0; dd < 32; dd++)
                sO[r*132 + lane*32 + dd] *= a;
        }
        __syncthreads();

        {
            int wn2 = (wid & 1) * 64;
            wmma::fragment<wmma::accumulator,16,16,16,float> oc[4];
            #pragma unroll
            for (int j = 0; j < 4; j++)
                wmma::load_matrix_sync(oc[j], sO + wm*132 + wn2 + j*16, 132, wmma::mem_row_major);
            #pragma unroll
            for (int kk = 0; kk < 4; kk++) {
                wmma::fragment<wmma::matrix_a,16,16,16,__half,wmma::row_major> pf;
                wmma::load_matrix_sync(pf, sP + wm*72 + kk*16, 72);
                #pragma unroll
                for (int j = 0; j < 4; j++) {
                    wmma::fragment<wmma::matrix_b,16,16,16,__half,wmma::row_major> vf;
                    wmma::load_matrix_sync(vf, sV + (kk*16)*136 + wn2 + j*16, 136);
                    wmma::mma_sync(oc[j], pf, vf, oc[j]);
                }
            }
            #pragma unroll
            for (int j = 0; j < 4; j++)
                wmma::store_matrix_sync(sO + wm*132 + wn2 + j*16, oc[j], 132, wmma::mem_row_major);
        }
        __syncthreads();
    }

    for (int v = tid; v < 64*128; v += 256) {
        int r = v >> 7, d = v & 127;
        float o = sO[r*132 + d] / sl[r];
        size_t dst = ((size_t)b * SEQ + q0 + r) * HID + (size_t)h * HDIM + d;
        __half hi, lo; splitf(o, hi, lo);
        g_AOhi[dst] = hi; g_AOlo[dst] = lo;
    }
}

// ---------------- launch ----------------
extern "C" void kernel_launch(void* const* d_in, const int* in_sizes, int n_in,
                              void* d_out, int out_size) {
    const float* X    = (const float*)d_in[0];
    const float* Wqkv = (const float*)d_in[1];
    const float* Wo   = (const float*)d_in[2];

    cudaFuncSetAttribute(flash_kernel, cudaFuncAttributeMaxDynamicSharedMemorySize, FL_SMEM);
    cudaFuncSetAttribute(gemm_qkv_i8_kernel, cudaFuncAttributeMaxDynamicSharedMemorySize, IGEMM_SMEM);
    cudaFuncSetAttribute(gemm_out_kernel, cudaFuncAttributeMaxDynamicSharedMemorySize, GEMM_SMEM);

    int8_t *Xh8, *Xl8, *Wqh8, *Wql8;
    float  *sX, *sW;
    __half *Woh, *Wol, *AOh, *AOl;
    cudaGetSymbolAddress((void**)&Xh8,  g_Xh8);
    cudaGetSymbolAddress((void**)&Xl8,  g_Xl8);
    cudaGetSymbolAddress((void**)&Wqh8, g_Wqh8);
    cudaGetSymbolAddress((void**)&Wql8, g_Wql8);
    cudaGetSymbolAddress((void**)&sX,   g_sX);
    cudaGetSymbolAddress((void**)&sW,   g_sW);
    cudaGetSymbolAddress((void**)&Woh,  g_Wohi);
    cudaGetSymbolAddress((void**)&Wol,  g_Wolo);
    cudaGetSymbolAddress((void**)&AOh,  g_AOhi);
    cudaGetSymbolAddress((void**)&AOl,  g_AOlo);

    quant_rows_kernel<<<MROWS, 256>>>(X,    Xh8,  Xl8,  sX, HID);
    quant_rows_kernel<<<QKVN,  256>>>(Wqkv, Wqh8, Wql8, sW, HID);
    split_wo_kernel  <<<(HID*HID + 255)/256, 256>>>(Wo);
    rope_table_kernel<<<(SEQ*64  + 255)/256, 256>>>();

    // QKV projection, int8 limb-split (M=4096, N=12288)
    gemm_qkv_i8_kernel<<<(MROWS/128)*(QKVN/128), 512, IGEMM_SMEM>>>(
        MROWS/128, QKVN/128);

    flash_kernel<<<dim3(SEQ/64, NHEAD, BATCH), 256, FL_SMEM>>>();

    // Output projection: fp16 2-term
    gemm_out_kernel<<<(MROWS/128)*(HID/128), 256, GEMM_SMEM>>>(
        AOh, AOl, Woh, Wol, (float*)d_out, HID, HID, MROWS/128, HID/128);
}

// round 10
// speedup vs baseline: 3.6847x; 3.6847x over previous
#include <cuda_runtime.h>
#include <cuda_fp16.h>
#include <mma.h>
#include <math.h>
#include <stdint.h>

using namespace nvcuda;

#define BATCH 2
#define SEQ   2048
#define HID   4096
#define NHEAD 32
#define HDIM  128
#define MROWS (BATCH*SEQ)     /* 4096 */
#define QKVN  (3*HID)         /* 12288 */

// ---------------- scratch ----------------
__device__ __half g_Xhi   [MROWS*HID];
__device__ __half g_Xlo   [MROWS*HID];
__device__ __half g_Wqkvhi[QKVN*HID];
__device__ __half g_Wqkvlo[QKVN*HID];
__device__ __half g_Wohi  [HID*HID];
__device__ __half g_Wolo  [HID*HID];
__device__ __half g_Qhi   [MROWS*HID];
__device__ __half g_Qlo   [MROWS*HID];
__device__ __half g_Khi   [MROWS*HID];
__device__ __half g_Klo   [MROWS*HID];
__device__ __half g_V     [MROWS*HID];
__device__ __half g_AO    [MROWS*HID];
__device__ float  g_cos   [SEQ*64];
__device__ float  g_sin   [SEQ*64];

__device__ __forceinline__ void splitf(float x, __half &hi, __half &lo) {
    hi = __float2half(x);
    lo = __float2half(x - __half2float(hi));
}

// ---------------- cp.async helpers ----------------
static __device__ __forceinline__ uint32_t smem_u32(const void* p) {
    uint32_t a;
    asm("{ .reg .u64 t; cvta.to.shared.u64 t, %1; cvt.u32.u64 %0, t; }" : "=r"(a) : "l"(p));
    return a;
}
static __device__ __forceinline__ void cp_async16(uint32_t dst, const void* src) {
    asm volatile("cp.async.cg.shared.global [%0], [%1], 16;\n" :: "r"(dst), "l"(src));
}
#define CP_COMMIT() asm volatile("cp.async.commit_group;\n" ::: "memory")
#define CP_WAIT1()  asm volatile("cp.async.wait_group 1;\n" ::: "memory")

// ---------------- elementwise split kernels ----------------
__device__ __forceinline__ void split_body(const float* __restrict__ src,
                                           __half* __restrict__ hi,
                                           __half* __restrict__ lo, int n) {
    int idx = blockIdx.x * blockDim.x + threadIdx.x;
    if (idx < n) {
        float x = src[idx];
        __half h, l; splitf(x, h, l);
        hi[idx] = h; lo[idx] = l;
    }
}
__global__ void __launch_bounds__(256) split_x_kernel(const float* __restrict__ src) {
    split_body(src, g_Xhi, g_Xlo, MROWS*HID);
}
__global__ void __launch_bounds__(256) split_wqkv_kernel(const float* __restrict__ src) {
    split_body(src, g_Wqkvhi, g_Wqkvlo, QKVN*HID);
}
__global__ void __launch_bounds__(256) split_wo_kernel(const float* __restrict__ src) {
    split_body(src, g_Wohi, g_Wolo, HID*HID);
}

// ---------------- RoPE cos/sin table ----------------
__global__ void __launch_bounds__(256) rope_table_kernel() {
    int idx = blockIdx.x * blockDim.x + threadIdx.x;
    if (idx >= SEQ*64) return;
    int i = idx & 63;
    int s = idx >> 6;
    double inv = pow(10000.0, -((double)(2*i)) / 128.0);
    float invf = (float)inv;
    float ang  = (float)s * invf;
    g_cos[idx] = (float)cos((double)ang);
    g_sin[idx] = (float)sin((double)ang);
}

// =====================================================================
//  Pipelined split-fp16 GEMM: CTA 128x128, 256 threads, warp 64x32.
//  KC=32, 2-stage cp.async, 2 CTAs/SM.
//  TERMS=3: AhiBhi+AhiBlo+AloBhi ; TERMS=2: AhiBhi+AhiBlo (Alo never loaded).
//  EPI: 0 = fp32 C direct ; 1 = fused RoPE+transpose+split (Q/K) ;
//       2 = direct fp16 V transpose.
// =====================================================================

#define KC        32
#define ARR_HALF  (128*40)                 /* 32 data halves + 8 pad */
#define STAGE_HALF (4*ARR_HALF)            /* 20480 */
#define STAGE_BYTES (STAGE_HALF*2)         /* 40960 */
#define GEMM_SMEM (2*STAGE_BYTES)          /* 81920 -> 2 CTAs/SM */

template<bool LOAD_ALO>
static __device__ __forceinline__ void gemm4_load_stage(
    uint32_t stage_base, int tid,
    const __half* __restrict__ Ahi, const __half* __restrict__ Alo,
    const __half* __restrict__ Bhi, const __half* __restrict__ Blo,
    int bm, int bn, int K, int k0)
{
    int chunk = tid & 3;        // 16B chunk within 64B data row
    int r0    = tid >> 2;       // 0..63
    const char* gAh = (const char*)(Ahi + (size_t)bm * K + k0) + chunk * 16;
    const char* gAl = (const char*)(Alo + (size_t)bm * K + k0) + chunk * 16;
    const char* gBh = (const char*)(Bhi + (size_t)bn * K + k0) + chunk * 16;
    const char* gBl = (const char*)(Blo + (size_t)bn * K + k0) + chunk * 16;
    #pragma unroll
    for (int u = 0; u < 2; u++) {
        int row = r0 + u * 64;
        uint32_t so = (uint32_t)(row * 80 + chunk * 16);
        cp_async16(stage_base + so,                 gAh + (size_t)row * K * 2);
        if (LOAD_ALO)
            cp_async16(stage_base + 2*ARR_HALF + so, gAl + (size_t)row * K * 2);
        cp_async16(stage_base + 4*ARR_HALF + so,    gBh + (size_t)row * K * 2);
        cp_async16(stage_base + 6*ARR_HALF + so,    gBl + (size_t)row * K * 2);
    }
}

template<int TERMS, int EPI>
static __device__ __forceinline__ void gemm_body(
    __half* smh, uint32_t smem_base, int tid, int wid,
    const __half* __restrict__ Ahi, const __half* __restrict__ Alo,
    const __half* __restrict__ Bhi, const __half* __restrict__ Blo,
    float* __restrict__ C, int K, int ldc, int bm, int bn)
{
    int wm = (wid >> 2) * 64;   // 2 warp rows of 64
    int wn = (wid & 3) * 32;    // 4 warp cols of 32

    wmma::fragment<wmma::accumulator,16,16,16,float> acc[4][2];
    #pragma unroll
    for (int i = 0; i < 4; i++)
        #pragma unroll
        for (int j = 0; j < 2; j++)
            wmma::fill_fragment(acc[i][j], 0.0f);

    const int NIT = K / KC;

    gemm4_load_stage<TERMS==3>(smem_base,               tid, Ahi, Alo, Bhi, Blo, bm, bn, K, 0);
    CP_COMMIT();
    gemm4_load_stage<TERMS==3>(smem_base + STAGE_BYTES, tid, Ahi, Alo, Bhi, Blo, bm, bn, K, KC);
    CP_COMMIT();

    for (int it = 0; it < NIT; it++) {
        CP_WAIT1();
        __syncthreads();

        const __half* st  = smh + (size_t)(it & 1) * STAGE_HALF;
        const __half* sAh = st;
        const __half* sAl = st + ARR_HALF;
        const __half* sBh = st + 2*ARR_HALF;
        const __half* sBl = st + 3*ARR_HALF;

        #pragma unroll
        for (int kk = 0; kk < 2; kk++) {
            wmma::fragment<wmma::matrix_b,16,16,16,__half,wmma::col_major> bh[2], bl[2];
            #pragma unroll
            for (int j = 0; j < 2; j++) {
                wmma::load_matrix_sync(bh[j], sBh + (wn + j*16)*40 + kk*16, 40);
                wmma::load_matrix_sync(bl[j], sBl + (wn + j*16)*40 + kk*16, 40);
            }
            #pragma unroll
            for (int i = 0; i < 4; i++) {
                wmma::fragment<wmma::matrix_a,16,16,16,__half,wmma::row_major> ah, al;
                wmma::load_matrix_sync(ah, sAh + (wm + i*16)*40 + kk*16, 40);
                if (TERMS == 3)
                    wmma::load_matrix_sync(al, sAl + (wm + i*16)*40 + kk*16, 40);
                #pragma unroll
                for (int j = 0; j < 2; j++) {
                    wmma::mma_sync(acc[i][j], ah, bh[j], acc[i][j]);
                    wmma::mma_sync(acc[i][j], ah, bl[j], acc[i][j]);
                    if (TERMS == 3)
                        wmma::mma_sync(acc[i][j], al, bh[j], acc[i][j]);
                }
            }
        }
        __syncthreads();

        int nxt = it + 2;
        if (nxt < NIT)
            gemm4_load_stage<TERMS==3>(smem_base + (uint32_t)(nxt & 1) * STAGE_BYTES, tid,
                                       Ahi, Alo, Bhi, Blo, bm, bn, K, nxt * KC);
        CP_COMMIT();
    }

    if (EPI == 0) {
        #pragma unroll
        for (int i = 0; i < 4; i++)
            #pragma unroll
            for (int j = 0; j < 2; j++) {
                size_t off = (size_t)(bm + wm + i*16) * ldc + bn + wn + j*16;
                wmma::store_matrix_sync(&C[off], acc[i][j], ldc, wmma::mem_row_major);
            }
        return;
    }

    // stage C tile (128 x 128, stride 132) in smem for fused epilogue
    float* sC = (float*)smh;
    #pragma unroll
    for (int i = 0; i < 4; i++)
        #pragma unroll
        for (int j = 0; j < 2; j++)
            wmma::store_matrix_sync(sC + (wm + i*16)*132 + wn + j*16, acc[i][j],
                                    132, wmma::mem_row_major);
    __syncthreads();

    int h = (bn >> 7) & 31;
    if (EPI == 1) {
        bool isk = (bn >= HID);
        __half* Dh = isk ? g_Khi : g_Qhi;
        __half* Dl = isk ? g_Klo : g_Qlo;
        for (int idx = tid; idx < 128*64; idx += 256) {
            int r = idx >> 6, d = idx & 63;
            float x1 = sC[r*132 + d];
            float x2 = sC[r*132 + d + 64];
            int row = bm + r;
            int s   = row & (SEQ-1);
            int b   = row >> 11;
            float c  = g_cos[s*64 + d];
            float sn = g_sin[s*64 + d];
            float o1 = x1*c - x2*sn;
            float o2 = x1*sn + x2*c;
            size_t dst = (((size_t)b * NHEAD + h) * SEQ + s) * HDIM + d;
            __half hi, lo;
            splitf(o1, hi, lo); Dh[dst]    = hi; Dl[dst]    = lo;
            splitf(o2, hi, lo); Dh[dst+64] = hi; Dl[dst+64] = lo;
        }
    } else {
        for (int idx = tid; idx < 128*128; idx += 256) {
            int r = idx >> 7, d = idx & 127;
            int row = bm + r;
            int s   = row & (SEQ-1);
            int b   = row >> 11;
            g_V[(((size_t)b * NHEAD + h) * SEQ + s) * HDIM + d] = __float2half(sC[r*132 + d]);
        }
    }
}

// merged QKV projection: bn < 2*HID -> Q/K (3-term, RoPE epi); else V (2-term)
__global__ void __launch_bounds__(256, 2) gemm_qkv_merged_kernel(
    const __half* __restrict__ Ahi, const __half* __restrict__ Alo,
    const __half* __restrict__ Bhi, const __half* __restrict__ Blo,
    int K, int grid_m, int grid_n)
{
    extern __shared__ __half smh[];
    uint32_t smem_base = smem_u32(smh);
    int tid = threadIdx.x;
    int wid = tid >> 5;

    int pid = blockIdx.x;
    const int GRPW = 16;
    int width = GRPW * grid_n;
    int g   = pid / width;
    int rem = pid - g * width;
    int gm  = grid_m - g * GRPW; if (gm > GRPW) gm = GRPW;
    int bm  = (g * GRPW + (rem % gm)) * 128;
    int bn  = (rem / gm) * 128;

    if (bn < 2*HID)
        gemm_body<3,1>(smh, smem_base, tid, wid, Ahi, Alo, Bhi, Blo,
                       nullptr, K, 0, bm, bn);
    else
        gemm_body<2,2>(smh, smem_base, tid, wid, Ahi, Alo, Bhi, Blo,
                       nullptr, K, 0, bm, bn);
}

// out projection: plain fp32 epilogue, 2-term (A is single fp16 array)
__global__ void __launch_bounds__(256, 2) gemm_out_kernel(
    const __half* __restrict__ Ahi,
    const __half* __restrict__ Bhi, const __half* __restrict__ Blo,
    float* __restrict__ C, int K, int ldc, int grid_m, int grid_n)
{
    extern __shared__ __half smh[];
    uint32_t smem_base = smem_u32(smh);
    int tid = threadIdx.x;
    int wid = tid >> 5;

    int pid = blockIdx.x;
    const int GRPW = 16;
    int width = GRPW * grid_n;
    int g   = pid / width;
    int rem = pid - g * width;
    int gm  = grid_m - g * GRPW; if (gm > GRPW) gm = GRPW;
    int bm  = (g * GRPW + (rem % gm)) * 128;
    int bn  = (rem / gm) * 128;

    gemm_body<2,0>(smh, smem_base, tid, wid, Ahi, Ahi, Bhi, Blo, C, K, ldc, bm, bn);
}

// ---------------- flash attention, 64-row q tiles, causal, cp.async double buffer ----------------
#define TILE_H   (64*136)
#define TILE_B   (TILE_H*2)
#define FL_SMEM  (8*TILE_B + 64*68*4 + 64*72*2 + 64*132*4 + 3*64*4)

static __device__ __forceinline__ void flash_issue_tile(
    uint32_t dKh, uint32_t dKl, uint32_t dV,
    const __half* __restrict__ Kh, const __half* __restrict__ Kl,
    const __half* __restrict__ V, int tid)
{
    int chunk = tid & 15;
    int r0    = tid >> 4;
    #pragma unroll
    for (int u = 0; u < 4; u++) {
        int r = r0 + u * 16;
        uint32_t so = (uint32_t)(r * 272 + chunk * 16);
        size_t   go = (size_t)r * HDIM * 2 + chunk * 16;
        cp_async16(dKh + so, (const char*)Kh + go);
        cp_async16(dKl + so, (const char*)Kl + go);
        cp_async16(dV  + so, (const char*)V  + go);
    }
}

__global__ void __launch_bounds__(256) flash_kernel() {
    extern __shared__ unsigned char smraw[];
    __half* sQh = (__half*)smraw;
    __half* sQl = sQh + TILE_H;
    __half* sKB = sQl + TILE_H;
    float*  sS  = (float*)(sKB + 6*TILE_H);
    __half* sP  = (__half*)(sS + 64*68);
    float*  sO  = (float*)(sP + 64*72);
    float*  smx = sO + 64*132;
    float*  sl  = smx + 64;

    int tid = threadIdx.x;
    int wid = tid >> 5;
    int qt  = gridDim.x - 1 - blockIdx.x;   // longest CTAs first
    int h   = blockIdx.y;
    int b   = blockIdx.z;
    int bh  = b * NHEAD + h;
    int q0  = qt * 64;

    const float scale = 0.08838834764831845f;

    const __half* Khg = g_Khi + (size_t)bh * SEQ * HDIM;
    const __half* Klg = g_Klo + (size_t)bh * SEQ * HDIM;
    const __half* Vg  = g_V   + (size_t)bh * SEQ * HDIM;

    uint32_t sKB_u = smem_u32(sKB);

    flash_issue_tile(sKB_u, sKB_u + TILE_B, sKB_u + 2*TILE_B, Khg, Klg, Vg, tid);
    CP_COMMIT();

    {
        const __half* Qh = g_Qhi + ((size_t)bh * SEQ + q0) * HDIM;
        const __half* Ql = g_Qlo + ((size_t)bh * SEQ + q0) * HDIM;
        for (int v = tid; v < 1024; v += 256) {
            int r = v >> 4, c = (v & 15) << 3;
            *(int4*)(sQh + r*136 + c) = *(const int4*)(Qh + r*HDIM + c);
            *(int4*)(sQl + r*136 + c) = *(const int4*)(Ql + r*HDIM + c);
        }
    }
    for (int v = tid; v < 64*132; v += 256) sO[v] = 0.0f;
    if (tid < 64) { smx[tid] = -INFINITY; sl[tid] = 0.0f; }

    int wm = (wid >> 1) * 16;

    for (int kt = 0; kt <= qt; kt++) {
        if (kt + 1 <= qt) {
            uint32_t nb = sKB_u + (uint32_t)((kt + 1) & 1) * 3 * TILE_B;
            flash_issue_tile(nb, nb + TILE_B, nb + 2*TILE_B,
                             Khg + (size_t)(kt+1)*64*HDIM,
                             Klg + (size_t)(kt+1)*64*HDIM,
                             Vg  + (size_t)(kt+1)*64*HDIM, tid);
        }
        CP_COMMIT();
        CP_WAIT1();
        __syncthreads();

        __half* sKh = sKB + (size_t)(kt & 1) * 3 * TILE_H;
        __half* sKl = sKh + TILE_H;
        __half* sV  = sKh + 2*TILE_H;

        // S = Q K^T (3-term split)
        {
            int wn = (wid & 1) * 32;
            wmma::fragment<wmma::accumulator,16,16,16,float> sacc[2];
            wmma::fill_fragment(sacc[0], 0.0f);
            wmma::fill_fragment(sacc[1], 0.0f);
            #pragma unroll
            for (int d8 = 0; d8 < 8; d8++) {
                wmma::fragment<wmma::matrix_a,16,16,16,__half,wmma::row_major> ah, al;
                wmma::load_matrix_sync(ah, sQh + wm*136 + d8*16, 136);
                wmma::load_matrix_sync(al, sQl + wm*136 + d8*16, 136);
                #pragma unroll
                for (int j = 0; j < 2; j++) {
                    wmma::fragment<wmma::matrix_b,16,16,16,__half,wmma::col_major> kh, kl;
                    wmma::load_matrix_sync(kh, sKh + (wn + j*16)*136 + d8*16, 136);
                    wmma::load_matrix_sync(kl, sKl + (wn + j*16)*136 + d8*16, 136);
                    wmma::mma_sync(sacc[j], ah, kh, sacc[j]);
                    wmma::mma_sync(sacc[j], ah, kl, sacc[j]);
                    wmma::mma_sync(sacc[j], al, kh, sacc[j]);
                }
            }
            wmma::store_matrix_sync(sS + wm*68 + wn,      sacc[0], 68, wmma::mem_row_major);
            wmma::store_matrix_sync(sS + wm*68 + wn + 16, sacc[1], 68, wmma::mem_row_major);
        }
        __syncthreads();

        // online softmax + fused O rescale (4 threads per row)
        {
            int r    = tid >> 2;
            int lane = tid & 3;
            bool diag = (kt == qt);
            int jmax = diag ? (r + 1) : 64;

            float lm = -INFINITY;
            #pragma unroll
            for (int jj = 0; jj < 16; jj++) {
                int j = lane*16 + jj;
                if (j < jmax) lm = fmaxf(lm, sS[r*68 + j] * scale);
            }
            lm = fmaxf(lm, __shfl_xor_sync(0xffffffffu, lm, 1));
            lm = fmaxf(lm, __shfl_xor_sync(0xffffffffu, lm, 2));
            float mo = smx[r];
            float mn = fmaxf(mo, lm);

            float rl = 0.0f;
            #pragma unroll
            for (int jj = 0; jj < 16; jj++) {
                int j = lane*16 + jj;
                float p = 0.0f;
                if (j < jmax) { p = __expf(sS[r*68 + j] * scale - mn); rl += p; }
                sP[r*72 + j] = __float2half(p);
            }
            rl += __shfl_xor_sync(0xffffffffu, rl, 1);
            rl += __shfl_xor_sync(0xffffffffu, rl, 2);

            float a = __expf(mo - mn);
            if (lane == 0) {
                smx[r] = mn;
                sl[r]  = sl[r] * a + rl;
            }
            #pragma unroll
            for (int dd = 0; dd < 32; dd++)
                sO[r*132 + lane*32 + dd] *= a;
        }
        __syncthreads();

        // O += P @ V
        {
            int wn2 = (wid & 1) * 64;
            wmma::fragment<wmma::accumulator,16,16,16,float> oc[4];
            #pragma unroll
            for (int j = 0; j < 4; j++)
                wmma::load_matrix_sync(oc[j], sO + wm*132 + wn2 + j*16, 132, wmma::mem_row_major);
            #pragma unroll
            for (int kk = 0; kk < 4; kk++) {
                wmma::fragment<wmma::matrix_a,16,16,16,__half,wmma::row_major> pf;
                wmma::load_matrix_sync(pf, sP + wm*72 + kk*16, 72);
                #pragma unroll
                for (int j = 0; j < 4; j++) {
                    wmma::fragment<wmma::matrix_b,16,16,16,__half,wmma::row_major> vf;
                    wmma::load_matrix_sync(vf, sV + (kk*16)*136 + wn2 + j*16, 136);
                    wmma::mma_sync(oc[j], pf, vf, oc[j]);
                }
            }
            #pragma unroll
            for (int j = 0; j < 4; j++)
                wmma::store_matrix_sync(sO + wm*132 + wn2 + j*16, oc[j], 132, wmma::mem_row_major);
        }
        __syncthreads();
    }

    // epilogue: normalize, merge heads, single fp16 output (out-proj is 2-term)
    for (int v = tid; v < 64*128; v += 256) {
        int r = v >> 7, d = v & 127;
        float o = sO[r*132 + d] / sl[r];
        size_t dst = ((size_t)b * SEQ + q0 + r) * HID + (size_t)h * HDIM + d;
        g_AO[dst] = __float2half(o);
    }
}

// ---------------- launch ----------------
extern "C" void kernel_launch(void* const* d_in, const int* in_sizes, int n_in,
                              void* d_out, int out_size) {
    const float* X    = (const float*)d_in[0];
    const float* Wqkv = (const float*)d_in[1];
    const float* Wo   = (const float*)d_in[2];

    cudaFuncSetAttribute(flash_kernel, cudaFuncAttributeMaxDynamicSharedMemorySize, FL_SMEM);
    cudaFuncSetAttribute(gemm_qkv_merged_kernel, cudaFuncAttributeMaxDynamicSharedMemorySize, GEMM_SMEM);
    cudaFuncSetAttribute(gemm_out_kernel, cudaFuncAttributeMaxDynamicSharedMemorySize, GEMM_SMEM);

    __half *Xhi, *Xlo, *Wqh, *Wql, *Woh, *Wol, *AO;
    cudaGetSymbolAddress((void**)&Xhi, g_Xhi);
    cudaGetSymbolAddress((void**)&Xlo, g_Xlo);
    cudaGetSymbolAddress((void**)&Wqh, g_Wqkvhi);
    cudaGetSymbolAddress((void**)&Wql, g_Wqkvlo);
    cudaGetSymbolAddress((void**)&Woh, g_Wohi);
    cudaGetSymbolAddress((void**)&Wol, g_Wolo);
    cudaGetSymbolAddress((void**)&AO,  g_AO);

    split_x_kernel   <<<(MROWS*HID + 255)/256, 256>>>(X);
    split_wqkv_kernel<<<(QKVN*HID  + 255)/256, 256>>>(Wqkv);
    split_wo_kernel  <<<(HID*HID   + 255)/256, 256>>>(Wo);
    rope_table_kernel<<<(SEQ*64    + 255)/256, 256>>>();

    // full QKV projection in one launch (M=4096, N=12288), 128x128 tiles
    gemm_qkv_merged_kernel<<<(MROWS/128)*(QKVN/128), 256, GEMM_SMEM>>>(
        Xhi, Xlo, Wqh, Wql, HID, MROWS/128, QKVN/128);

    flash_kernel<<<dim3(SEQ/64, NHEAD, BATCH), 256, FL_SMEM>>>();

    // Output projection (N=4096): 2-term, direct fp32 store
    gemm_out_kernel<<<(MROWS/128)*(HID/128), 256, GEMM_SMEM>>>(
        AO, Woh, Wol, (float*)d_out, HID, HID, MROWS/128, HID/128);
}

// round 11
// speedup vs baseline: 4.3321x; 1.1757x over previous
#include <cuda_runtime.h>
#include <cuda_fp16.h>
#include <mma.h>
#include <math.h>
#include <stdint.h>

using namespace nvcuda;

#define BATCH 2
#define SEQ   2048
#define HID   4096
#define NHEAD 32
#define HDIM  128
#define MROWS (BATCH*SEQ)     /* 4096 */
#define QKVN  (3*HID)         /* 12288 */

// ---------------- scratch ----------------
__device__ __half g_Xhi   [MROWS*HID];
__device__ __half g_Wqkvhi[QKVN*HID];
__device__ __half g_Wqkvlo[QKVN*HID];
__device__ __half g_Wohi  [HID*HID];
__device__ __half g_Wolo  [HID*HID];
__device__ __half g_Qhi   [MROWS*HID];
__device__ __half g_Qlo   [MROWS*HID];
__device__ __half g_Khi   [MROWS*HID];
__device__ __half g_Klo   [MROWS*HID];
__device__ __half g_V     [MROWS*HID];
__device__ __half g_AO    [MROWS*HID];
__device__ float  g_cos   [SEQ*64];
__device__ float  g_sin   [SEQ*64];

__device__ __forceinline__ void splitf(float x, __half &hi, __half &lo) {
    hi = __float2half(x);
    lo = __float2half(x - __half2float(hi));
}

// ---------------- cp.async helpers ----------------
static __device__ __forceinline__ uint32_t smem_u32(const void* p) {
    uint32_t a;
    asm("{ .reg .u64 t; cvta.to.shared.u64 t, %1; cvt.u32.u64 %0, t; }" : "=r"(a) : "l"(p));
    return a;
}
static __device__ __forceinline__ void cp_async16(uint32_t dst, const void* src) {
    asm volatile("cp.async.cg.shared.global [%0], [%1], 16;\n" :: "r"(dst), "l"(src));
}
#define CP_COMMIT() asm volatile("cp.async.commit_group;\n" ::: "memory")
#define CP_WAIT1()  asm volatile("cp.async.wait_group 1;\n" ::: "memory")

// ---------------- elementwise kernels ----------------
__global__ void __launch_bounds__(256) conv_x_kernel(const float* __restrict__ src) {
    int idx = blockIdx.x * blockDim.x + threadIdx.x;
    if (idx < MROWS*HID) g_Xhi[idx] = __float2half(src[idx]);
}
__device__ __forceinline__ void split_body(const float* __restrict__ src,
                                           __half* __restrict__ hi,
                                           __half* __restrict__ lo, int n) {
    int idx = blockIdx.x * blockDim.x + threadIdx.x;
    if (idx < n) {
        float x = src[idx];
        __half h, l; splitf(x, h, l);
        hi[idx] = h; lo[idx] = l;
    }
}
__global__ void __launch_bounds__(256) split_wqkv_kernel(const float* __restrict__ src) {
    split_body(src, g_Wqkvhi, g_Wqkvlo, QKVN*HID);
}
__global__ void __launch_bounds__(256) split_wo_kernel(const float* __restrict__ src) {
    split_body(src, g_Wohi, g_Wolo, HID*HID);
}

// ---------------- RoPE cos/sin table ----------------
__global__ void __launch_bounds__(256) rope_table_kernel() {
    int idx = blockIdx.x * blockDim.x + threadIdx.x;
    if (idx >= SEQ*64) return;
    int i = idx & 63;
    int s = idx >> 6;
    double inv = pow(10000.0, -((double)(2*i)) / 128.0);
    float invf = (float)inv;
    float ang  = (float)s * invf;
    g_cos[idx] = (float)cos((double)ang);
    g_sin[idx] = (float)sin((double)ang);
}

// =====================================================================
//  Pipelined split-fp16 GEMM: CTA 128x128, 256 threads, warp 64x32.
//  KC=32, 2-stage cp.async, 2 CTAs/SM. 2-term: AhiBhi + AhiBlo.
//  EPI: 0 = fp32 C direct ; 1 = fused RoPE+transpose+split (Q/K) ;
//       2 = direct fp16 V transpose.
// =====================================================================

#define KC        32
#define ARR_HALF  (128*40)                 /* 32 data halves + 8 pad */
#define STAGE_HALF (4*ARR_HALF)            /* 20480 */
#define STAGE_BYTES (STAGE_HALF*2)         /* 40960 */
#define GEMM_SMEM (2*STAGE_BYTES)          /* 81920 -> 2 CTAs/SM */

static __device__ __forceinline__ void gemm_load_stage(
    uint32_t stage_base, int tid,
    const __half* __restrict__ Ahi,
    const __half* __restrict__ Bhi, const __half* __restrict__ Blo,
    int bm, int bn, int K, int k0)
{
    int chunk = tid & 3;        // 16B chunk within 64B data row
    int r0    = tid >> 2;       // 0..63
    const char* gAh = (const char*)(Ahi + (size_t)bm * K + k0) + chunk * 16;
    const char* gBh = (const char*)(Bhi + (size_t)bn * K + k0) + chunk * 16;
    const char* gBl = (const char*)(Blo + (size_t)bn * K + k0) + chunk * 16;
    #pragma unroll
    for (int u = 0; u < 2; u++) {
        int row = r0 + u * 64;
        uint32_t so = (uint32_t)(row * 80 + chunk * 16);
        cp_async16(stage_base + so,                 gAh + (size_t)row * K * 2);
        cp_async16(stage_base + 4*ARR_HALF + so,    gBh + (size_t)row * K * 2);
        cp_async16(stage_base + 6*ARR_HALF + so,    gBl + (size_t)row * K * 2);
    }
}

template<int EPI>
static __device__ __forceinline__ void gemm_body(
    __half* smh, uint32_t smem_base, int tid, int wid,
    const __half* __restrict__ Ahi,
    const __half* __restrict__ Bhi, const __half* __restrict__ Blo,
    float* __restrict__ C, int K, int ldc, int bm, int bn)
{
    int wm = (wid >> 2) * 64;   // 2 warp rows of 64
    int wn = (wid & 3) * 32;    // 4 warp cols of 32

    wmma::fragment<wmma::accumulator,16,16,16,float> acc[4][2];
    #pragma unroll
    for (int i = 0; i < 4; i++)
        #pragma unroll
        for (int j = 0; j < 2; j++)
            wmma::fill_fragment(acc[i][j], 0.0f);

    const int NIT = K / KC;

    gemm_load_stage(smem_base,               tid, Ahi, Bhi, Blo, bm, bn, K, 0);
    CP_COMMIT();
    gemm_load_stage(smem_base + STAGE_BYTES, tid, Ahi, Bhi, Blo, bm, bn, K, KC);
    CP_COMMIT();

    for (int it = 0; it < NIT; it++) {
        CP_WAIT1();
        __syncthreads();

        const __half* st  = smh + (size_t)(it & 1) * STAGE_HALF;
        const __half* sAh = st;
        const __half* sBh = st + 2*ARR_HALF;
        const __half* sBl = st + 3*ARR_HALF;

        #pragma unroll
        for (int kk = 0; kk < 2; kk++) {
            wmma::fragment<wmma::matrix_b,16,16,16,__half,wmma::col_major> bh[2], bl[2];
            #pragma unroll
            for (int j = 0; j < 2; j++) {
                wmma::load_matrix_sync(bh[j], sBh + (wn + j*16)*40 + kk*16, 40);
                wmma::load_matrix_sync(bl[j], sBl + (wn + j*16)*40 + kk*16, 40);
            }
            #pragma unroll
            for (int i = 0; i < 4; i++) {
                wmma::fragment<wmma::matrix_a,16,16,16,__half,wmma::row_major> ah;
                wmma::load_matrix_sync(ah, sAh + (wm + i*16)*40 + kk*16, 40);
                #pragma unroll
                for (int j = 0; j < 2; j++) {
                    wmma::mma_sync(acc[i][j], ah, bh[j], acc[i][j]);
                    wmma::mma_sync(acc[i][j], ah, bl[j], acc[i][j]);
                }
            }
        }
        __syncthreads();

        int nxt = it + 2;
        if (nxt < NIT)
            gemm_load_stage(smem_base + (uint32_t)(nxt & 1) * STAGE_BYTES, tid,
                            Ahi, Bhi, Blo, bm, bn, K, nxt * KC);
        CP_COMMIT();
    }

    if (EPI == 0) {
        #pragma unroll
        for (int i = 0; i < 4; i++)
            #pragma unroll
            for (int j = 0; j < 2; j++) {
                size_t off = (size_t)(bm + wm + i*16) * ldc + bn + wn + j*16;
                wmma::store_matrix_sync(&C[off], acc[i][j], ldc, wmma::mem_row_major);
            }
        return;
    }

    // stage C tile (128 x 128, stride 132) in smem for fused epilogue
    float* sC = (float*)smh;
    #pragma unroll
    for (int i = 0; i < 4; i++)
        #pragma unroll
        for (int j = 0; j < 2; j++)
            wmma::store_matrix_sync(sC + (wm + i*16)*132 + wn + j*16, acc[i][j],
                                    132, wmma::mem_row_major);
    __syncthreads();

    int h = (bn >> 7) & 31;
    if (EPI == 1) {
        bool isk = (bn >= HID);
        __half* Dh = isk ? g_Khi : g_Qhi;
        __half* Dl = isk ? g_Klo : g_Qlo;
        for (int idx = tid; idx < 128*64; idx += 256) {
            int r = idx >> 6, d = idx & 63;
            float x1 = sC[r*132 + d];
            float x2 = sC[r*132 + d + 64];
            int row = bm + r;
            int s   = row & (SEQ-1);
            int b   = row >> 11;
            float c  = g_cos[s*64 + d];
            float sn = g_sin[s*64 + d];
            float o1 = x1*c - x2*sn;
            float o2 = x1*sn + x2*c;
            size_t dst = (((size_t)b * NHEAD + h) * SEQ + s) * HDIM + d;
            __half hi, lo;
            splitf(o1, hi, lo); Dh[dst]    = hi; Dl[dst]    = lo;
            splitf(o2, hi, lo); Dh[dst+64] = hi; Dl[dst+64] = lo;
        }
    } else {
        for (int idx = tid; idx < 128*128; idx += 256) {
            int r = idx >> 7, d = idx & 127;
            int row = bm + r;
            int s   = row & (SEQ-1);
            int b   = row >> 11;
            g_V[(((size_t)b * NHEAD + h) * SEQ + s) * HDIM + d] = __float2half(sC[r*132 + d]);
        }
    }
}

// merged QKV projection: all columns 2-term; Q/K epi=RoPE, V epi=fp16 transpose
__global__ void __launch_bounds__(256, 2) gemm_qkv_merged_kernel(
    const __half* __restrict__ Ahi,
    const __half* __restrict__ Bhi, const __half* __restrict__ Blo,
    int K, int grid_m, int grid_n)
{
    extern __shared__ __half smh[];
    uint32_t smem_base = smem_u32(smh);
    int tid = threadIdx.x;
    int wid = tid >> 5;

    int pid = blockIdx.x;
    const int GRPW = 16;
    int width = GRPW * grid_n;
    int g   = pid / width;
    int rem = pid - g * width;
    int gm  = grid_m - g * GRPW; if (gm > GRPW) gm = GRPW;
    int bm  = (g * GRPW + (rem % gm)) * 128;
    int bn  = (rem / gm) * 128;

    if (bn < 2*HID)
        gemm_body<1>(smh, smem_base, tid, wid, Ahi, Bhi, Blo, nullptr, K, 0, bm, bn);
    else
        gemm_body<2>(smh, smem_base, tid, wid, Ahi, Bhi, Blo, nullptr, K, 0, bm, bn);
}

// out projection: plain fp32 epilogue, 2-term
__global__ void __launch_bounds__(256, 2) gemm_out_kernel(
    const __half* __restrict__ Ahi,
    const __half* __restrict__ Bhi, const __half* __restrict__ Blo,
    float* __restrict__ C, int K, int ldc, int grid_m, int grid_n)
{
    extern __shared__ __half smh[];
    uint32_t smem_base = smem_u32(smh);
    int tid = threadIdx.x;
    int wid = tid >> 5;

    int pid = blockIdx.x;
    const int GRPW = 16;
    int width = GRPW * grid_n;
    int g   = pid / width;
    int rem = pid - g * width;
    int gm  = grid_m - g * GRPW; if (gm > GRPW) gm = GRPW;
    int bm  = (g * GRPW + (rem % gm)) * 128;
    int bn  = (rem / gm) * 128;

    gemm_body<0>(smh, smem_base, tid, wid, Ahi, Bhi, Blo, C, K, ldc, bm, bn);
}

// ---------------- flash attention, 64-row q tiles, causal, cp.async double buffer ----------------
#define TILE_H   (64*136)
#define TILE_B   (TILE_H*2)
#define FL_SMEM  (8*TILE_B + 64*68*4 + 64*72*2 + 64*132*4 + 3*64*4)

static __device__ __forceinline__ void flash_issue_tile(
    uint32_t dKh, uint32_t dKl, uint32_t dV,
    const __half* __restrict__ Kh, const __half* __restrict__ Kl,
    const __half* __restrict__ V, int tid)
{
    int chunk = tid & 15;
    int r0    = tid >> 4;
    #pragma unroll
    for (int u = 0; u < 4; u++) {
        int r = r0 + u * 16;
        uint32_t so = (uint32_t)(r * 272 + chunk * 16);
        size_t   go = (size_t)r * HDIM * 2 + chunk * 16;
        cp_async16(dKh + so, (const char*)Kh + go);
        cp_async16(dKl + so, (const char*)Kl + go);
        cp_async16(dV  + so, (const char*)V  + go);
    }
}

__global__ void __launch_bounds__(256) flash_kernel() {
    extern __shared__ unsigned char smraw[];
    __half* sQh = (__half*)smraw;
    __half* sQl = sQh + TILE_H;
    __half* sKB = sQl + TILE_H;
    float*  sS  = (float*)(sKB + 6*TILE_H);
    __half* sP  = (__half*)(sS + 64*68);
    float*  sO  = (float*)(sP + 64*72);
    float*  smx = sO + 64*132;
    float*  sl  = smx + 64;

    int tid = threadIdx.x;
    int wid = tid >> 5;
    int qt  = gridDim.x - 1 - blockIdx.x;   // longest CTAs first
    int h   = blockIdx.y;
    int b   = blockIdx.z;
    int bh  = b * NHEAD + h;
    int q0  = qt * 64;

    const float scale = 0.08838834764831845f;

    const __half* Khg = g_Khi + (size_t)bh * SEQ * HDIM;
    const __half* Klg = g_Klo + (size_t)bh * SEQ * HDIM;
    const __half* Vg  = g_V   + (size_t)bh * SEQ * HDIM;

    uint32_t sKB_u = smem_u32(sKB);

    flash_issue_tile(sKB_u, sKB_u + TILE_B, sKB_u + 2*TILE_B, Khg, Klg, Vg, tid);
    CP_COMMIT();

    {
        const __half* Qh = g_Qhi + ((size_t)bh * SEQ + q0) * HDIM;
        const __half* Ql = g_Qlo + ((size_t)bh * SEQ + q0) * HDIM;
        for (int v = tid; v < 1024; v += 256) {
            int r = v >> 4, c = (v & 15) << 3;
            *(int4*)(sQh + r*136 + c) = *(const int4*)(Qh + r*HDIM + c);
            *(int4*)(sQl + r*136 + c) = *(const int4*)(Ql + r*HDIM + c);
        }
    }
    for (int v = tid; v < 64*132; v += 256) sO[v] = 0.0f;
    if (tid < 64) { smx[tid] = -INFINITY; sl[tid] = 0.0f; }

    int wm = (wid >> 1) * 16;

    for (int kt = 0; kt <= qt; kt++) {
        if (kt + 1 <= qt) {
            uint32_t nb = sKB_u + (uint32_t)((kt + 1) & 1) * 3 * TILE_B;
            flash_issue_tile(nb, nb + TILE_B, nb + 2*TILE_B,
                             Khg + (size_t)(kt+1)*64*HDIM,
                             Klg + (size_t)(kt+1)*64*HDIM,
                             Vg  + (size_t)(kt+1)*64*HDIM, tid);
        }
        CP_COMMIT();
        CP_WAIT1();
        __syncthreads();

        __half* sKh = sKB + (size_t)(kt & 1) * 3 * TILE_H;
        __half* sKl = sKh + TILE_H;
        __half* sV  = sKh + 2*TILE_H;

        // S = Q K^T (3-term split)
        {
            int wn = (wid & 1) * 32;
            wmma::fragment<wmma::accumulator,16,16,16,float> sacc[2];
            wmma::fill_fragment(sacc[0], 0.0f);
            wmma::fill_fragment(sacc[1], 0.0f);
            #pragma unroll
            for (int d8 = 0; d8 < 8; d8++) {
                wmma::fragment<wmma::matrix_a,16,16,16,__half,wmma::row_major> ah, al;
                wmma::load_matrix_sync(ah, sQh + wm*136 + d8*16, 136);
                wmma::load_matrix_sync(al, sQl + wm*136 + d8*16, 136);
                #pragma unroll
                for (int j = 0; j < 2; j++) {
                    wmma::fragment<wmma::matrix_b,16,16,16,__half,wmma::col_major> kh, kl;
                    wmma::load_matrix_sync(kh, sKh + (wn + j*16)*136 + d8*16, 136);
                    wmma::load_matrix_sync(kl, sKl + (wn + j*16)*136 + d8*16, 136);
                    wmma::mma_sync(sacc[j], ah, kh, sacc[j]);
                    wmma::mma_sync(sacc[j], ah, kl, sacc[j]);
                    wmma::mma_sync(sacc[j], al, kh, sacc[j]);
                }
            }
            wmma::store_matrix_sync(sS + wm*68 + wn,      sacc[0], 68, wmma::mem_row_major);
            wmma::store_matrix_sync(sS + wm*68 + wn + 16, sacc[1], 68, wmma::mem_row_major);
        }
        __syncthreads();

        // online softmax + fused O rescale (4 threads per row)
        {
            int r    = tid >> 2;
            int lane = tid & 3;
            bool diag = (kt == qt);
            int jmax = diag ? (r + 1) : 64;

            float lm = -INFINITY;
            #pragma unroll
            for (int jj = 0; jj < 16; jj++) {
                int j = lane*16 + jj;
                if (j < jmax) lm = fmaxf(lm, sS[r*68 + j] * scale);
            }
            lm = fmaxf(lm, __shfl_xor_sync(0xffffffffu, lm, 1));
            lm = fmaxf(lm, __shfl_xor_sync(0xffffffffu, lm, 2));
            float mo = smx[r];
            float mn = fmaxf(mo, lm);

            float rl = 0.0f;
            #pragma unroll
            for (int jj = 0; jj < 16; jj++) {
                int j = lane*16 + jj;
                float p = 0.0f;
                if (j < jmax) { p = __expf(sS[r*68 + j] * scale - mn); rl += p; }
                sP[r*72 + j] = __float2half(p);
            }
            rl += __shfl_xor_sync(0xffffffffu, rl, 1);
            rl += __shfl_xor_sync(0xffffffffu, rl, 2);

            float a = __expf(mo - mn);
            if (lane == 0) {
                smx[r] = mn;
                sl[r]  = sl[r] * a + rl;
            }
            #pragma unroll
            for (int dd = 0; dd < 32; dd++)
                sO[r*132 + lane*32 + dd] *= a;
        }
        __syncthreads();

        // O += P @ V
        {
            int wn2 = (wid & 1) * 64;
            wmma::fragment<wmma::accumulator,16,16,16,float> oc[4];
            #pragma unroll
            for (int j = 0; j < 4; j++)
                wmma::load_matrix_sync(oc[j], sO + wm*132 + wn2 + j*16, 132, wmma::mem_row_major);
            #pragma unroll
            for (int kk = 0; kk < 4; kk++) {
                wmma::fragment<wmma::matrix_a,16,16,16,__half,wmma::row_major> pf;
                wmma::load_matrix_sync(pf, sP + wm*72 + kk*16, 72);
                #pragma unroll
                for (int j = 0; j < 4; j++) {
                    wmma::fragment<wmma::matrix_b,16,16,16,__half,wmma::row_major> vf;
                    wmma::load_matrix_sync(vf, sV + (kk*16)*136 + wn2 + j*16, 136);
                    wmma::mma_sync(oc[j], pf, vf, oc[j]);
                }
            }
            #pragma unroll
            for (int j = 0; j < 4; j++)
                wmma::store_matrix_sync(sO + wm*132 + wn2 + j*16, oc[j], 132, wmma::mem_row_major);
        }
        __syncthreads();
    }

    // epilogue: normalize, merge heads, single fp16 output
    for (int v = tid; v < 64*128; v += 256) {
        int r = v >> 7, d = v & 127;
        float o = sO[r*132 + d] / sl[r];
        size_t dst = ((size_t)b * SEQ + q0 + r) * HID + (size_t)h * HDIM + d;
        g_AO[dst] = __float2half(o);
    }
}

// ---------------- launch ----------------
extern "C" void kernel_launch(void* const* d_in, const int* in_sizes, int n_in,
                              void* d_out, int out_size) {
    const float* X    = (const float*)d_in[0];
    const float* Wqkv = (const float*)d_in[1];
    const float* Wo   = (const float*)d_in[2];

    cudaFuncSetAttribute(flash_kernel, cudaFuncAttributeMaxDynamicSharedMemorySize, FL_SMEM);
    cudaFuncSetAttribute(gemm_qkv_merged_kernel, cudaFuncAttributeMaxDynamicSharedMemorySize, GEMM_SMEM);
    cudaFuncSetAttribute(gemm_out_kernel, cudaFuncAttributeMaxDynamicSharedMemorySize, GEMM_SMEM);

    __half *Xhi, *Wqh, *Wql, *Woh, *Wol, *AO;
    cudaGetSymbolAddress((void**)&Xhi, g_Xhi);
    cudaGetSymbolAddress((void**)&Wqh, g_Wqkvhi);
    cudaGetSymbolAddress((void**)&Wql, g_Wqkvlo);
    cudaGetSymbolAddress((void**)&Woh, g_Wohi);
    cudaGetSymbolAddress((void**)&Wol, g_Wolo);
    cudaGetSymbolAddress((void**)&AO,  g_AO);

    conv_x_kernel    <<<(MROWS*HID + 255)/256, 256>>>(X);
    split_wqkv_kernel<<<(QKVN*HID  + 255)/256, 256>>>(Wqkv);
    split_wo_kernel  <<<(HID*HID   + 255)/256, 256>>>(Wo);
    rope_table_kernel<<<(SEQ*64    + 255)/256, 256>>>();

    // full QKV projection in one launch (M=4096, N=12288), 2-term everywhere
    gemm_qkv_merged_kernel<<<(MROWS/128)*(QKVN/128), 256, GEMM_SMEM>>>(
        Xhi, Wqh, Wql, HID, MROWS/128, QKVN/128);

    flash_kernel<<<dim3(SEQ/64, NHEAD, BATCH), 256, FL_SMEM>>>();

    // Output projection (N=4096): 2-term, direct fp32 store
    gemm_out_kernel<<<(MROWS/128)*(HID/128), 256, GEMM_SMEM>>>(
        AO, Woh, Wol, (float*)d_out, HID, HID, MROWS/128, HID/128);
}

// round 12
// speedup vs baseline: 5.2856x; 1.2201x over previous
#include <cuda_runtime.h>
#include <cuda_fp16.h>
#include <mma.h>
#include <math.h>
#include <stdint.h>

using namespace nvcuda;

#define BATCH 2
#define SEQ   2048
#define HID   4096
#define NHEAD 32
#define HDIM  128
#define MROWS (BATCH*SEQ)     /* 4096 */
#define QKVN  (3*HID)         /* 12288 */

// ---------------- scratch ----------------
__device__ __half g_Xhi   [MROWS*HID];
__device__ __half g_Wqkvhi[QKVN*HID];
__device__ __half g_Wqkvlo[QKVN*HID];
__device__ __half g_Wohi  [HID*HID];
__device__ __half g_Qhi   [MROWS*HID];
__device__ __half g_Qlo   [MROWS*HID];
__device__ __half g_Khi   [MROWS*HID];
__device__ __half g_V     [MROWS*HID];
__device__ __half g_AO    [MROWS*HID];
__device__ float  g_cos   [SEQ*64];
__device__ float  g_sin   [SEQ*64];

__device__ __forceinline__ void splitf(float x, __half &hi, __half &lo) {
    hi = __float2half(x);
    lo = __float2half(x - __half2float(hi));
}

// ---------------- cp.async helpers ----------------
static __device__ __forceinline__ uint32_t smem_u32(const void* p) {
    uint32_t a;
    asm("{ .reg .u64 t; cvta.to.shared.u64 t, %1; cvt.u32.u64 %0, t; }" : "=r"(a) : "l"(p));
    return a;
}
static __device__ __forceinline__ void cp_async16(uint32_t dst, const void* src) {
    asm volatile("cp.async.cg.shared.global [%0], [%1], 16;\n" :: "r"(dst), "l"(src));
}
#define CP_COMMIT() asm volatile("cp.async.commit_group;\n" ::: "memory")
#define CP_WAIT1()  asm volatile("cp.async.wait_group 1;\n" ::: "memory")

// ---------------- elementwise kernels ----------------
__global__ void __launch_bounds__(256) conv_x_kernel(const float* __restrict__ src) {
    int idx = blockIdx.x * blockDim.x + threadIdx.x;
    if (idx < MROWS*HID) g_Xhi[idx] = __float2half(src[idx]);
}
__global__ void __launch_bounds__(256) split_wqkv_kernel(const float* __restrict__ src) {
    int idx = blockIdx.x * blockDim.x + threadIdx.x;
    if (idx < QKVN*HID) {
        float x = src[idx];
        __half h, l; splitf(x, h, l);
        g_Wqkvhi[idx] = h; g_Wqkvlo[idx] = l;
    }
}
__global__ void __launch_bounds__(256) conv_wo_kernel(const float* __restrict__ src) {
    int idx = blockIdx.x * blockDim.x + threadIdx.x;
    if (idx < HID*HID) g_Wohi[idx] = __float2half(src[idx]);
}

// ---------------- RoPE cos/sin table ----------------
__global__ void __launch_bounds__(256) rope_table_kernel() {
    int idx = blockIdx.x * blockDim.x + threadIdx.x;
    if (idx >= SEQ*64) return;
    int i = idx & 63;
    int s = idx >> 6;
    double inv = pow(10000.0, -((double)(2*i)) / 128.0);
    float invf = (float)inv;
    float ang  = (float)s * invf;
    g_cos[idx] = (float)cos((double)ang);
    g_sin[idx] = (float)sin((double)ang);
}

// =====================================================================
//  Pipelined fp16 GEMM: CTA 128x128, 256 threads, warp 64x32.
//  KC=32, 2-stage cp.async, 2 CTAs/SM.
//  BTERMS=2: A·Bhi + A·Blo ; BTERMS=1: A·Bhi.
//  EPI: 0 = fp32 C direct ; 1 = fused RoPE+transpose (Q: hi/lo, K: hi) ;
//       2 = direct fp16 V transpose.
// =====================================================================

#define KC        32
#define ARR_HALF  (128*40)                 /* 32 data halves + 8 pad */
#define STAGE_HALF (4*ARR_HALF)            /* 20480 */
#define STAGE_BYTES (STAGE_HALF*2)         /* 40960 */
#define GEMM_SMEM (2*STAGE_BYTES)          /* 81920 -> 2 CTAs/SM */

template<int BTERMS>
static __device__ __forceinline__ void gemm_load_stage(
    uint32_t stage_base, int tid,
    const __half* __restrict__ Ahi,
    const __half* __restrict__ Bhi, const __half* __restrict__ Blo,
    int bm, int bn, int K, int k0)
{
    int chunk = tid & 3;        // 16B chunk within 64B data row
    int r0    = tid >> 2;       // 0..63
    const char* gAh = (const char*)(Ahi + (size_t)bm * K + k0) + chunk * 16;
    const char* gBh = (const char*)(Bhi + (size_t)bn * K + k0) + chunk * 16;
    const char* gBl = (const char*)(Blo + (size_t)bn * K + k0) + chunk * 16;
    #pragma unroll
    for (int u = 0; u < 2; u++) {
        int row = r0 + u * 64;
        uint32_t so = (uint32_t)(row * 80 + chunk * 16);
        cp_async16(stage_base + so,              gAh + (size_t)row * K * 2);
        cp_async16(stage_base + 4*ARR_HALF + so, gBh + (size_t)row * K * 2);
        if (BTERMS == 2)
            cp_async16(stage_base + 6*ARR_HALF + so, gBl + (size_t)row * K * 2);
    }
}

template<int BTERMS, int EPI>
static __device__ __forceinline__ void gemm_body(
    __half* smh, uint32_t smem_base, int tid, int wid,
    const __half* __restrict__ Ahi,
    const __half* __restrict__ Bhi, const __half* __restrict__ Blo,
    float* __restrict__ C, int K, int ldc, int bm, int bn)
{
    int wm = (wid >> 2) * 64;   // 2 warp rows of 64
    int wn = (wid & 3) * 32;    // 4 warp cols of 32

    wmma::fragment<wmma::accumulator,16,16,16,float> acc[4][2];
    #pragma unroll
    for (int i = 0; i < 4; i++)
        #pragma unroll
        for (int j = 0; j < 2; j++)
            wmma::fill_fragment(acc[i][j], 0.0f);

    const int NIT = K / KC;

    gemm_load_stage<BTERMS>(smem_base,               tid, Ahi, Bhi, Blo, bm, bn, K, 0);
    CP_COMMIT();
    gemm_load_stage<BTERMS>(smem_base + STAGE_BYTES, tid, Ahi, Bhi, Blo, bm, bn, K, KC);
    CP_COMMIT();

    for (int it = 0; it < NIT; it++) {
        CP_WAIT1();
        __syncthreads();

        const __half* st  = smh + (size_t)(it & 1) * STAGE_HALF;
        const __half* sAh = st;
        const __half* sBh = st + 2*ARR_HALF;
        const __half* sBl = st + 3*ARR_HALF;

        #pragma unroll
        for (int kk = 0; kk < 2; kk++) {
            wmma::fragment<wmma::matrix_b,16,16,16,__half,wmma::col_major> bh[2], bl[2];
            #pragma unroll
            for (int j = 0; j < 2; j++) {
                wmma::load_matrix_sync(bh[j], sBh + (wn + j*16)*40 + kk*16, 40);
                if (BTERMS == 2)
                    wmma::load_matrix_sync(bl[j], sBl + (wn + j*16)*40 + kk*16, 40);
            }
            #pragma unroll
            for (int i = 0; i < 4; i++) {
                wmma::fragment<wmma::matrix_a,16,16,16,__half,wmma::row_major> ah;
                wmma::load_matrix_sync(ah, sAh + (wm + i*16)*40 + kk*16, 40);
                #pragma unroll
                for (int j = 0; j < 2; j++) {
                    wmma::mma_sync(acc[i][j], ah, bh[j], acc[i][j]);
                    if (BTERMS == 2)
                        wmma::mma_sync(acc[i][j], ah, bl[j], acc[i][j]);
                }
            }
        }
        __syncthreads();

        int nxt = it + 2;
        if (nxt < NIT)
            gemm_load_stage<BTERMS>(smem_base + (uint32_t)(nxt & 1) * STAGE_BYTES, tid,
                                    Ahi, Bhi, Blo, bm, bn, K, nxt * KC);
        CP_COMMIT();
    }

    if (EPI == 0) {
        #pragma unroll
        for (int i = 0; i < 4; i++)
            #pragma unroll
            for (int j = 0; j < 2; j++) {
                size_t off = (size_t)(bm + wm + i*16) * ldc + bn + wn + j*16;
                wmma::store_matrix_sync(&C[off], acc[i][j], ldc, wmma::mem_row_major);
            }
        return;
    }

    // stage C tile (128 x 128, stride 132) in smem for fused epilogue
    float* sC = (float*)smh;
    #pragma unroll
    for (int i = 0; i < 4; i++)
        #pragma unroll
        for (int j = 0; j < 2; j++)
            wmma::store_matrix_sync(sC + (wm + i*16)*132 + wn + j*16, acc[i][j],
                                    132, wmma::mem_row_major);
    __syncthreads();

    int h = (bn >> 7) & 31;
    if (EPI == 1) {
        bool isk = (bn >= HID);
        for (int idx = tid; idx < 128*64; idx += 256) {
            int r = idx >> 6, d = idx & 63;
            float x1 = sC[r*132 + d];
            float x2 = sC[r*132 + d + 64];
            int row = bm + r;
            int s   = row & (SEQ-1);
            int b   = row >> 11;
            float c  = g_cos[s*64 + d];
            float sn = g_sin[s*64 + d];
            float o1 = x1*c - x2*sn;
            float o2 = x1*sn + x2*c;
            size_t dst = (((size_t)b * NHEAD + h) * SEQ + s) * HDIM + d;
            if (isk) {
                g_Khi[dst]    = __float2half(o1);
                g_Khi[dst+64] = __float2half(o2);
            } else {
                __half hi, lo;
                splitf(o1, hi, lo); g_Qhi[dst]    = hi; g_Qlo[dst]    = lo;
                splitf(o2, hi, lo); g_Qhi[dst+64] = hi; g_Qlo[dst+64] = lo;
            }
        }
    } else {
        for (int idx = tid; idx < 128*128; idx += 256) {
            int r = idx >> 7, d = idx & 127;
            int row = bm + r;
            int s   = row & (SEQ-1);
            int b   = row >> 11;
            g_V[(((size_t)b * NHEAD + h) * SEQ + s) * HDIM + d] = __float2half(sC[r*132 + d]);
        }
    }
}

// merged QKV projection: Q/K cols 2-Bterm + RoPE epi; V cols 1-Bterm + fp16 epi
__global__ void __launch_bounds__(256, 2) gemm_qkv_merged_kernel(
    const __half* __restrict__ Ahi,
    const __half* __restrict__ Bhi, const __half* __restrict__ Blo,
    int K, int grid_m, int grid_n)
{
    extern __shared__ __half smh[];
    uint32_t smem_base = smem_u32(smh);
    int tid = threadIdx.x;
    int wid = tid >> 5;

    int pid = blockIdx.x;
    const int GRPW = 16;
    int width = GRPW * grid_n;
    int g   = pid / width;
    int rem = pid - g * width;
    int gm  = grid_m - g * GRPW; if (gm > GRPW) gm = GRPW;
    int bm  = (g * GRPW + (rem % gm)) * 128;
    int bn  = (rem / gm) * 128;

    if (bn < 2*HID)
        gemm_body<2,1>(smh, smem_base, tid, wid, Ahi, Bhi, Blo, nullptr, K, 0, bm, bn);
    else
        gemm_body<1,2>(smh, smem_base, tid, wid, Ahi, Bhi, Blo, nullptr, K, 0, bm, bn);
}

// out projection: pure fp16, fp32 epilogue
__global__ void __launch_bounds__(256, 2) gemm_out_kernel(
    const __half* __restrict__ Ahi, const __half* __restrict__ Bhi,
    float* __restrict__ C, int K, int ldc, int grid_m, int grid_n)
{
    extern __shared__ __half smh[];
    uint32_t smem_base = smem_u32(smh);
    int tid = threadIdx.x;
    int wid = tid >> 5;

    int pid = blockIdx.x;
    const int GRPW = 16;
    int width = GRPW * grid_n;
    int g   = pid / width;
    int rem = pid - g * width;
    int gm  = grid_m - g * GRPW; if (gm > GRPW) gm = GRPW;
    int bm  = (g * GRPW + (rem % gm)) * 128;
    int bn  = (rem / gm) * 128;

    gemm_body<1,0>(smh, smem_base, tid, wid, Ahi, Bhi, Bhi, C, K, ldc, bm, bn);
}

// ---------------- flash attention: Q hi/lo x K fp16, causal, double buffer ----------------
#define TILE_H   (64*136)
#define TILE_B   (TILE_H*2)
#define FL_SMEM  (6*TILE_B + 64*68*4 + 64*72*2 + 64*132*4 + 3*64*4)

static __device__ __forceinline__ void flash_issue_tile(
    uint32_t dKh, uint32_t dV,
    const __half* __restrict__ Kh, const __half* __restrict__ V, int tid)
{
    int chunk = tid & 15;
    int r0    = tid >> 4;
    #pragma unroll
    for (int u = 0; u < 4; u++) {
        int r = r0 + u * 16;
        uint32_t so = (uint32_t)(r * 272 + chunk * 16);
        size_t   go = (size_t)r * HDIM * 2 + chunk * 16;
        cp_async16(dKh + so, (const char*)Kh + go);
        cp_async16(dV  + so, (const char*)V  + go);
    }
}

__global__ void __launch_bounds__(256) flash_kernel() {
    extern __shared__ unsigned char smraw[];
    __half* sQh = (__half*)smraw;
    __half* sQl = sQh + TILE_H;
    __half* sKB = sQl + TILE_H;              // 2 buffers x (Kh, V)
    float*  sS  = (float*)(sKB + 4*TILE_H);
    __half* sP  = (__half*)(sS + 64*68);
    float*  sO  = (float*)(sP + 64*72);
    float*  smx = sO + 64*132;
    float*  sl  = smx + 64;

    int tid = threadIdx.x;
    int wid = tid >> 5;
    int qt  = gridDim.x - 1 - blockIdx.x;   // longest CTAs first
    int h   = blockIdx.y;
    int b   = blockIdx.z;
    int bh  = b * NHEAD + h;
    int q0  = qt * 64;

    const float scale = 0.08838834764831845f;

    const __half* Khg = g_Khi + (size_t)bh * SEQ * HDIM;
    const __half* Vg  = g_V   + (size_t)bh * SEQ * HDIM;

    uint32_t sKB_u = smem_u32(sKB);

    flash_issue_tile(sKB_u, sKB_u + TILE_B, Khg, Vg, tid);
    CP_COMMIT();

    {
        const __half* Qh = g_Qhi + ((size_t)bh * SEQ + q0) * HDIM;
        const __half* Ql = g_Qlo + ((size_t)bh * SEQ + q0) * HDIM;
        for (int v = tid; v < 1024; v += 256) {
            int r = v >> 4, c = (v & 15) << 3;
            *(int4*)(sQh + r*136 + c) = *(const int4*)(Qh + r*HDIM + c);
            *(int4*)(sQl + r*136 + c) = *(const int4*)(Ql + r*HDIM + c);
        }
    }
    for (int v = tid; v < 64*132; v += 256) sO[v] = 0.0f;
    if (tid < 64) { smx[tid] = -INFINITY; sl[tid] = 0.0f; }

    int wm = (wid >> 1) * 16;

    for (int kt = 0; kt <= qt; kt++) {
        if (kt + 1 <= qt) {
            uint32_t nb = sKB_u + (uint32_t)((kt + 1) & 1) * 2 * TILE_B;
            flash_issue_tile(nb, nb + TILE_B,
                             Khg + (size_t)(kt+1)*64*HDIM,
                             Vg  + (size_t)(kt+1)*64*HDIM, tid);
        }
        CP_COMMIT();
        CP_WAIT1();
        __syncthreads();

        __half* sKh = sKB + (size_t)(kt & 1) * 2 * TILE_H;
        __half* sV  = sKh + TILE_H;

        // S = (Qhi + Qlo) K^T   (K pure fp16)
        {
            int wn = (wid & 1) * 32;
            wmma::fragment<wmma::accumulator,16,16,16,float> sacc[2];
            wmma::fill_fragment(sacc[0], 0.0f);
            wmma::fill_fragment(sacc[1], 0.0f);
            #pragma unroll
            for (int d8 = 0; d8 < 8; d8++) {
                wmma::fragment<wmma::matrix_a,16,16,16,__half,wmma::row_major> ah, al;
                wmma::load_matrix_sync(ah, sQh + wm*136 + d8*16, 136);
                wmma::load_matrix_sync(al, sQl + wm*136 + d8*16, 136);
                #pragma unroll
                for (int j = 0; j < 2; j++) {
                    wmma::fragment<wmma::matrix_b,16,16,16,__half,wmma::col_major> kh;
                    wmma::load_matrix_sync(kh, sKh + (wn + j*16)*136 + d8*16, 136);
                    wmma::mma_sync(sacc[j], ah, kh, sacc[j]);
                    wmma::mma_sync(sacc[j], al, kh, sacc[j]);
                }
            }
            wmma::store_matrix_sync(sS + wm*68 + wn,      sacc[0], 68, wmma::mem_row_major);
            wmma::store_matrix_sync(sS + wm*68 + wn + 16, sacc[1], 68, wmma::mem_row_major);
        }
        __syncthreads();

        // online softmax + fused O rescale (4 threads per row)
        {
            int r    = tid >> 2;
            int lane = tid & 3;
            bool diag = (kt == qt);
            int jmax = diag ? (r + 1) : 64;

            float lm = -INFINITY;
            #pragma unroll
            for (int jj = 0; jj < 16; jj++) {
                int j = lane*16 + jj;
                if (j < jmax) lm = fmaxf(lm, sS[r*68 + j] * scale);
            }
            lm = fmaxf(lm, __shfl_xor_sync(0xffffffffu, lm, 1));
            lm = fmaxf(lm, __shfl_xor_sync(0xffffffffu, lm, 2));
            float mo = smx[r];
            float mn = fmaxf(mo, lm);

            float rl = 0.0f;
            #pragma unroll
            for (int jj = 0; jj < 16; jj++) {
                int j = lane*16 + jj;
                float p = 0.0f;
                if (j < jmax) { p = __expf(sS[r*68 + j] * scale - mn); rl += p; }
                sP[r*72 + j] = __float2half(p);
            }
            rl += __shfl_xor_sync(0xffffffffu, rl, 1);
            rl += __shfl_xor_sync(0xffffffffu, rl, 2);

            float a = __expf(mo - mn);
            if (lane == 0) {
                smx[r] = mn;
                sl[r]  = sl[r] * a + rl;
            }
            #pragma unroll
            for (int dd = 0; dd < 32; dd++)
                sO[r*132 + lane*32 + dd] *= a;
        }
        __syncthreads();

        // O += P @ V
        {
            int wn2 = (wid & 1) * 64;
            wmma::fragment<wmma::accumulator,16,16,16,float> oc[4];
            #pragma unroll
            for (int j = 0; j < 4; j++)
                wmma::load_matrix_sync(oc[j], sO + wm*132 + wn2 + j*16, 132, wmma::mem_row_major);
            #pragma unroll
            for (int kk = 0; kk < 4; kk++) {
                wmma::fragment<wmma::matrix_a,16,16,16,__half,wmma::row_major> pf;
                wmma::load_matrix_sync(pf, sP + wm*72 + kk*16, 72);
                #pragma unroll
                for (int j = 0; j < 4; j++) {
                    wmma::fragment<wmma::matrix_b,16,16,16,__half,wmma::row_major> vf;
                    wmma::load_matrix_sync(vf, sV + (kk*16)*136 + wn2 + j*16, 136);
                    wmma::mma_sync(oc[j], pf, vf, oc[j]);
                }
            }
            #pragma unroll
            for (int j = 0; j < 4; j++)
                wmma::store_matrix_sync(sO + wm*132 + wn2 + j*16, oc[j], 132, wmma::mem_row_major);
        }
        __syncthreads();
    }

    // epilogue: normalize, merge heads, single fp16 output
    for (int v = tid; v < 64*128; v += 256) {
        int r = v >> 7, d = v & 127;
        float o = sO[r*132 + d] / sl[r];
        size_t dst = ((size_t)b * SEQ + q0 + r) * HID + (size_t)h * HDIM + d;
        g_AO[dst] = __float2half(o);
    }
}

// ---------------- launch ----------------
extern "C" void kernel_launch(void* const* d_in, const int* in_sizes, int n_in,
                              void* d_out, int out_size) {
    const float* X    = (const float*)d_in[0];
    const float* Wqkv = (const float*)d_in[1];
    const float* Wo   = (const float*)d_in[2];

    cudaFuncSetAttribute(flash_kernel, cudaFuncAttributeMaxDynamicSharedMemorySize, FL_SMEM);
    cudaFuncSetAttribute(gemm_qkv_merged_kernel, cudaFuncAttributeMaxDynamicSharedMemorySize, GEMM_SMEM);
    cudaFuncSetAttribute(gemm_out_kernel, cudaFuncAttributeMaxDynamicSharedMemorySize, GEMM_SMEM);

    __half *Xhi, *Wqh, *Wql, *Woh, *AO;
    cudaGetSymbolAddress((void**)&Xhi, g_Xhi);
    cudaGetSymbolAddress((void**)&Wqh, g_Wqkvhi);
    cudaGetSymbolAddress((void**)&Wql, g_Wqkvlo);
    cudaGetSymbolAddress((void**)&Woh, g_Wohi);
    cudaGetSymbolAddress((void**)&AO,  g_AO);

    conv_x_kernel    <<<(MROWS*HID + 255)/256, 256>>>(X);
    split_wqkv_kernel<<<(QKVN*HID  + 255)/256, 256>>>(Wqkv);
    conv_wo_kernel   <<<(HID*HID   + 255)/256, 256>>>(Wo);
    rope_table_kernel<<<(SEQ*64    + 255)/256, 256>>>();

    // full QKV projection in one launch (M=4096, N=12288)
    gemm_qkv_merged_kernel<<<(MROWS/128)*(QKVN/128), 256, GEMM_SMEM>>>(
        Xhi, Wqh, Wql, HID, MROWS/128, QKVN/128);

    flash_kernel<<<dim3(SEQ/64, NHEAD, BATCH), 256, FL_SMEM>>>();

    // Output projection (N=4096): pure fp16
    gemm_out_kernel<<<(MROWS/128)*(HID/128), 256, GEMM_SMEM>>>(
        AO, Woh, (float*)d_out, HID, HID, MROWS/128, HID/128);
}

// round 13
// speedup vs baseline: 5.3401x; 1.0103x over previous
#include <cuda_runtime.h>
#include <cuda_fp16.h>
#include <mma.h>
#include <math.h>
#include <stdint.h>

using namespace nvcuda;

#define BATCH 2
#define SEQ   2048
#define HID   4096
#define NHEAD 32
#define HDIM  128
#define MROWS (BATCH*SEQ)     /* 4096 */
#define QKVN  (3*HID)         /* 12288 */

// ---------------- scratch ----------------
__device__ __half g_Xhi   [MROWS*HID];
__device__ __half g_Wqkvhi[QKVN*HID];
__device__ __half g_Wqkvlo[QKVN*HID];
__device__ __half g_Wohi  [HID*HID];
__device__ __half g_Qhi   [MROWS*HID];
__device__ __half g_Khi   [MROWS*HID];
__device__ __half g_V     [MROWS*HID];
__device__ __half g_AO    [MROWS*HID];
__device__ float  g_cos   [SEQ*64];
__device__ float  g_sin   [SEQ*64];

__device__ __forceinline__ void splitf(float x, __half &hi, __half &lo) {
    hi = __float2half(x);
    lo = __float2half(x - __half2float(hi));
}

// ---------------- cp.async helpers ----------------
static __device__ __forceinline__ uint32_t smem_u32(const void* p) {
    uint32_t a;
    asm("{ .reg .u64 t; cvta.to.shared.u64 t, %1; cvt.u32.u64 %0, t; }" : "=r"(a) : "l"(p));
    return a;
}
static __device__ __forceinline__ void cp_async16(uint32_t dst, const void* src) {
    asm volatile("cp.async.cg.shared.global [%0], [%1], 16;\n" :: "r"(dst), "l"(src));
}
#define CP_COMMIT() asm volatile("cp.async.commit_group;\n" ::: "memory")
#define CP_WAIT1()  asm volatile("cp.async.wait_group 1;\n" ::: "memory")

// ---------------- elementwise kernels ----------------
__global__ void __launch_bounds__(256) conv_x_kernel(const float* __restrict__ src) {
    int idx = blockIdx.x * blockDim.x + threadIdx.x;
    if (idx < MROWS*HID) g_Xhi[idx] = __float2half(src[idx]);
}
__global__ void __launch_bounds__(256) split_wqkv_kernel(const float* __restrict__ src) {
    int idx = blockIdx.x * blockDim.x + threadIdx.x;
    if (idx < QKVN*HID) {
        float x = src[idx];
        __half h, l; splitf(x, h, l);
        g_Wqkvhi[idx] = h; g_Wqkvlo[idx] = l;
    }
}
__global__ void __launch_bounds__(256) conv_wo_kernel(const float* __restrict__ src) {
    int idx = blockIdx.x * blockDim.x + threadIdx.x;
    if (idx < HID*HID) g_Wohi[idx] = __float2half(src[idx]);
}

// ---------------- RoPE cos/sin table ----------------
__global__ void __launch_bounds__(256) rope_table_kernel() {
    int idx = blockIdx.x * blockDim.x + threadIdx.x;
    if (idx >= SEQ*64) return;
    int i = idx & 63;
    int s = idx >> 6;
    double inv = pow(10000.0, -((double)(2*i)) / 128.0);
    float invf = (float)inv;
    float ang  = (float)s * invf;
    g_cos[idx] = (float)cos((double)ang);
    g_sin[idx] = (float)sin((double)ang);
}

// =====================================================================
//  Pipelined fp16 GEMM: CTA 128x128, 256 threads, warp 64x32.
//  KC=32, 2-stage cp.async, 2 CTAs/SM.
//  BTERMS=2: A·Bhi + A·Blo ; BTERMS=1: A·Bhi.
//  EPI: 0 = fp32 C direct ; 1 = fused RoPE+transpose fp16 (Q/K) ;
//       2 = direct fp16 V transpose.
// =====================================================================

#define KC        32
#define ARR_HALF  (128*40)                 /* 32 data halves + 8 pad */
#define STAGE_HALF (4*ARR_HALF)            /* 20480 */
#define STAGE_BYTES (STAGE_HALF*2)         /* 40960 */
#define GEMM_SMEM (2*STAGE_BYTES)          /* 81920 -> 2 CTAs/SM */

template<int BTERMS>
static __device__ __forceinline__ void gemm_load_stage(
    uint32_t stage_base, int tid,
    const __half* __restrict__ Ahi,
    const __half* __restrict__ Bhi, const __half* __restrict__ Blo,
    int bm, int bn, int K, int k0)
{
    int chunk = tid & 3;        // 16B chunk within 64B data row
    int r0    = tid >> 2;       // 0..63
    const char* gAh = (const char*)(Ahi + (size_t)bm * K + k0) + chunk * 16;
    const char* gBh = (const char*)(Bhi + (size_t)bn * K + k0) + chunk * 16;
    const char* gBl = (const char*)(Blo + (size_t)bn * K + k0) + chunk * 16;
    #pragma unroll
    for (int u = 0; u < 2; u++) {
        int row = r0 + u * 64;
        uint32_t so = (uint32_t)(row * 80 + chunk * 16);
        cp_async16(stage_base + so,              gAh + (size_t)row * K * 2);
        cp_async16(stage_base + 4*ARR_HALF + so, gBh + (size_t)row * K * 2);
        if (BTERMS == 2)
            cp_async16(stage_base + 6*ARR_HALF + so, gBl + (size_t)row * K * 2);
    }
}

template<int BTERMS, int EPI>
static __device__ __forceinline__ void gemm_body(
    __half* smh, uint32_t smem_base, int tid, int wid,
    const __half* __restrict__ Ahi,
    const __half* __restrict__ Bhi, const __half* __restrict__ Blo,
    float* __restrict__ C, int K, int ldc, int bm, int bn)
{
    int wm = (wid >> 2) * 64;   // 2 warp rows of 64
    int wn = (wid & 3) * 32;    // 4 warp cols of 32

    wmma::fragment<wmma::accumulator,16,16,16,float> acc[4][2];
    #pragma unroll
    for (int i = 0; i < 4; i++)
        #pragma unroll
        for (int j = 0; j < 2; j++)
            wmma::fill_fragment(acc[i][j], 0.0f);

    const int NIT = K / KC;

    gemm_load_stage<BTERMS>(smem_base,               tid, Ahi, Bhi, Blo, bm, bn, K, 0);
    CP_COMMIT();
    gemm_load_stage<BTERMS>(smem_base + STAGE_BYTES, tid, Ahi, Bhi, Blo, bm, bn, K, KC);
    CP_COMMIT();

    for (int it = 0; it < NIT; it++) {
        CP_WAIT1();
        __syncthreads();

        const __half* st  = smh + (size_t)(it & 1) * STAGE_HALF;
        const __half* sAh = st;
        const __half* sBh = st + 2*ARR_HALF;
        const __half* sBl = st + 3*ARR_HALF;

        #pragma unroll
        for (int kk = 0; kk < 2; kk++) {
            wmma::fragment<wmma::matrix_b,16,16,16,__half,wmma::col_major> bh[2], bl[2];
            #pragma unroll
            for (int j = 0; j < 2; j++) {
                wmma::load_matrix_sync(bh[j], sBh + (wn + j*16)*40 + kk*16, 40);
                if (BTERMS == 2)
                    wmma::load_matrix_sync(bl[j], sBl + (wn + j*16)*40 + kk*16, 40);
            }
            #pragma unroll
            for (int i = 0; i < 4; i++) {
                wmma::fragment<wmma::matrix_a,16,16,16,__half,wmma::row_major> ah;
                wmma::load_matrix_sync(ah, sAh + (wm + i*16)*40 + kk*16, 40);
                #pragma unroll
                for (int j = 0; j < 2; j++) {
                    wmma::mma_sync(acc[i][j], ah, bh[j], acc[i][j]);
                    if (BTERMS == 2)
                        wmma::mma_sync(acc[i][j], ah, bl[j], acc[i][j]);
                }
            }
        }
        __syncthreads();

        int nxt = it + 2;
        if (nxt < NIT)
            gemm_load_stage<BTERMS>(smem_base + (uint32_t)(nxt & 1) * STAGE_BYTES, tid,
                                    Ahi, Bhi, Blo, bm, bn, K, nxt * KC);
        CP_COMMIT();
    }

    if (EPI == 0) {
        #pragma unroll
        for (int i = 0; i < 4; i++)
            #pragma unroll
            for (int j = 0; j < 2; j++) {
                size_t off = (size_t)(bm + wm + i*16) * ldc + bn + wn + j*16;
                wmma::store_matrix_sync(&C[off], acc[i][j], ldc, wmma::mem_row_major);
            }
        return;
    }

    // stage C tile (128 x 128, stride 132) in smem for fused epilogue
    float* sC = (float*)smh;
    #pragma unroll
    for (int i = 0; i < 4; i++)
        #pragma unroll
        for (int j = 0; j < 2; j++)
            wmma::store_matrix_sync(sC + (wm + i*16)*132 + wn + j*16, acc[i][j],
                                    132, wmma::mem_row_major);
    __syncthreads();

    int h = (bn >> 7) & 31;
    if (EPI == 1) {
        __half* D = (bn >= HID) ? g_Khi : g_Qhi;
        for (int idx = tid; idx < 128*64; idx += 256) {
            int r = idx >> 6, d = idx & 63;
            float x1 = sC[r*132 + d];
            float x2 = sC[r*132 + d + 64];
            int row = bm + r;
            int s   = row & (SEQ-1);
            int b   = row >> 11;
            float c  = g_cos[s*64 + d];
            float sn = g_sin[s*64 + d];
            size_t dst = (((size_t)b * NHEAD + h) * SEQ + s) * HDIM + d;
            D[dst]    = __float2half(x1*c - x2*sn);
            D[dst+64] = __float2half(x1*sn + x2*c);
        }
    } else {
        for (int idx = tid; idx < 128*128; idx += 256) {
            int r = idx >> 7, d = idx & 127;
            int row = bm + r;
            int s   = row & (SEQ-1);
            int b   = row >> 11;
            g_V[(((size_t)b * NHEAD + h) * SEQ + s) * HDIM + d] = __float2half(sC[r*132 + d]);
        }
    }
}

// merged QKV projection: Q/K cols 2-Bterm + RoPE epi; V cols 1-Bterm + fp16 epi
__global__ void __launch_bounds__(256, 2) gemm_qkv_merged_kernel(
    const __half* __restrict__ Ahi,
    const __half* __restrict__ Bhi, const __half* __restrict__ Blo,
    int K, int grid_m, int grid_n)
{
    extern __shared__ __half smh[];
    uint32_t smem_base = smem_u32(smh);
    int tid = threadIdx.x;
    int wid = tid >> 5;

    int pid = blockIdx.x;
    const int GRPW = 16;
    int width = GRPW * grid_n;
    int g   = pid / width;
    int rem = pid - g * width;
    int gm  = grid_m - g * GRPW; if (gm > GRPW) gm = GRPW;
    int bm  = (g * GRPW + (rem % gm)) * 128;
    int bn  = (rem / gm) * 128;

    if (bn < 2*HID)
        gemm_body<2,1>(smh, smem_base, tid, wid, Ahi, Bhi, Blo, nullptr, K, 0, bm, bn);
    else
        gemm_body<1,2>(smh, smem_base, tid, wid, Ahi, Bhi, Blo, nullptr, K, 0, bm, bn);
}

// out projection: pure fp16, fp32 epilogue
__global__ void __launch_bounds__(256, 2) gemm_out_kernel(
    const __half* __restrict__ Ahi, const __half* __restrict__ Bhi,
    float* __restrict__ C, int K, int ldc, int grid_m, int grid_n)
{
    extern __shared__ __half smh[];
    uint32_t smem_base = smem_u32(smh);
    int tid = threadIdx.x;
    int wid = tid >> 5;

    int pid = blockIdx.x;
    const int GRPW = 16;
    int width = GRPW * grid_n;
    int g   = pid / width;
    int rem = pid - g * width;
    int gm  = grid_m - g * GRPW; if (gm > GRPW) gm = GRPW;
    int bm  = (g * GRPW + (rem % gm)) * 128;
    int bn  = (rem / gm) * 128;

    gemm_body<1,0>(smh, smem_base, tid, wid, Ahi, Bhi, Bhi, C, K, ldc, bm, bn);
}

// ---------------- flash attention: pure fp16 Q/K/V, fp32 accum, causal ----------------
#define TILE_H   (64*136)
#define TILE_B   (TILE_H*2)
#define FL_SMEM  (5*TILE_B + 64*68*4 + 64*72*2 + 64*132*4 + 3*64*4)

static __device__ __forceinline__ void flash_issue_tile(
    uint32_t dKh, uint32_t dV,
    const __half* __restrict__ Kh, const __half* __restrict__ V, int tid)
{
    int chunk = tid & 15;
    int r0    = tid >> 4;
    #pragma unroll
    for (int u = 0; u < 4; u++) {
        int r = r0 + u * 16;
        uint32_t so = (uint32_t)(r * 272 + chunk * 16);
        size_t   go = (size_t)r * HDIM * 2 + chunk * 16;
        cp_async16(dKh + so, (const char*)Kh + go);
        cp_async16(dV  + so, (const char*)V  + go);
    }
}

__global__ void __launch_bounds__(256) flash_kernel() {
    extern __shared__ unsigned char smraw[];
    __half* sQh = (__half*)smraw;
    __half* sKB = sQh + TILE_H;              // 2 buffers x (Kh, V)
    float*  sS  = (float*)(sKB + 4*TILE_H);
    __half* sP  = (__half*)(sS + 64*68);
    float*  sO  = (float*)(sP + 64*72);
    float*  smx = sO + 64*132;
    float*  sl  = smx + 64;

    int tid = threadIdx.x;
    int wid = tid >> 5;
    int qt  = gridDim.x - 1 - blockIdx.x;   // longest CTAs first
    int h   = blockIdx.y;
    int b   = blockIdx.z;
    int bh  = b * NHEAD + h;
    int q0  = qt * 64;

    const float scale = 0.08838834764831845f;

    const __half* Khg = g_Khi + (size_t)bh * SEQ * HDIM;
    const __half* Vg  = g_V   + (size_t)bh * SEQ * HDIM;

    uint32_t sKB_u = smem_u32(sKB);

    flash_issue_tile(sKB_u, sKB_u + TILE_B, Khg, Vg, tid);
    CP_COMMIT();

    {
        const __half* Qh = g_Qhi + ((size_t)bh * SEQ + q0) * HDIM;
        for (int v = tid; v < 1024; v += 256) {
            int r = v >> 4, c = (v & 15) << 3;
            *(int4*)(sQh + r*136 + c) = *(const int4*)(Qh + r*HDIM + c);
        }
    }
    for (int v = tid; v < 64*132; v += 256) sO[v] = 0.0f;
    if (tid < 64) { smx[tid] = -INFINITY; sl[tid] = 0.0f; }

    int wm = (wid >> 1) * 16;

    for (int kt = 0; kt <= qt; kt++) {
        if (kt + 1 <= qt) {
            uint32_t nb = sKB_u + (uint32_t)((kt + 1) & 1) * 2 * TILE_B;
            flash_issue_tile(nb, nb + TILE_B,
                             Khg + (size_t)(kt+1)*64*HDIM,
                             Vg  + (size_t)(kt+1)*64*HDIM, tid);
        }
        CP_COMMIT();
        CP_WAIT1();
        __syncthreads();

        __half* sKh = sKB + (size_t)(kt & 1) * 2 * TILE_H;
        __half* sV  = sKh + TILE_H;

        // S = Q K^T (pure fp16 inputs, fp32 accum)
        {
            int wn = (wid & 1) * 32;
            wmma::fragment<wmma::accumulator,16,16,16,float> sacc[2];
            wmma::fill_fragment(sacc[0], 0.0f);
            wmma::fill_fragment(sacc[1], 0.0f);
            #pragma unroll
            for (int d8 = 0; d8 < 8; d8++) {
                wmma::fragment<wmma::matrix_a,16,16,16,__half,wmma::row_major> ah;
                wmma::load_matrix_sync(ah, sQh + wm*136 + d8*16, 136);
                #pragma unroll
                for (int j = 0; j < 2; j++) {
                    wmma::fragment<wmma::matrix_b,16,16,16,__half,wmma::col_major> kh;
                    wmma::load_matrix_sync(kh, sKh + (wn + j*16)*136 + d8*16, 136);
                    wmma::mma_sync(sacc[j], ah, kh, sacc[j]);
                }
            }
            wmma::store_matrix_sync(sS + wm*68 + wn,      sacc[0], 68, wmma::mem_row_major);
            wmma::store_matrix_sync(sS + wm*68 + wn + 16, sacc[1], 68, wmma::mem_row_major);
        }
        __syncthreads();

        // online softmax + fused O rescale (4 threads per row)
        {
            int r    = tid >> 2;
            int lane = tid & 3;
            bool diag = (kt == qt);
            int jmax = diag ? (r + 1) : 64;

            float lm = -INFINITY;
            #pragma unroll
            for (int jj = 0; jj < 16; jj++) {
                int j = lane*16 + jj;
                if (j < jmax) lm = fmaxf(lm, sS[r*68 + j] * scale);
            }
            lm = fmaxf(lm, __shfl_xor_sync(0xffffffffu, lm, 1));
            lm = fmaxf(lm, __shfl_xor_sync(0xffffffffu, lm, 2));
            float mo = smx[r];
            float mn = fmaxf(mo, lm);

            float rl = 0.0f;
            #pragma unroll
            for (int jj = 0; jj < 16; jj++) {
                int j = lane*16 + jj;
                float p = 0.0f;
                if (j < jmax) { p = __expf(sS[r*68 + j] * scale - mn); rl += p; }
                sP[r*72 + j] = __float2half(p);
            }
            rl += __shfl_xor_sync(0xffffffffu, rl, 1);
            rl += __shfl_xor_sync(0xffffffffu, rl, 2);

            float a = __expf(mo - mn);
            if (lane == 0) {
                smx[r] = mn;
                sl[r]  = sl[r] * a + rl;
            }
            #pragma unroll
            for (int dd = 0; dd < 32; dd++)
                sO[r*132 + lane*32 + dd] *= a;
        }
        __syncthreads();

        // O += P @ V
        {
            int wn2 = (wid & 1) * 64;
            wmma::fragment<wmma::accumulator,16,16,16,float> oc[4];
            #pragma unroll
            for (int j = 0; j < 4; j++)
                wmma::load_matrix_sync(oc[j], sO + wm*132 + wn2 + j*16, 132, wmma::mem_row_major);
            #pragma unroll
            for (int kk = 0; kk < 4; kk++) {
                wmma::fragment<wmma::matrix_a,16,16,16,__half,wmma::row_major> pf;
                wmma::load_matrix_sync(pf, sP + wm*72 + kk*16, 72);
                #pragma unroll
                for (int j = 0; j < 4; j++) {
                    wmma::fragment<wmma::matrix_b,16,16,16,__half,wmma::row_major> vf;
                    wmma::load_matrix_sync(vf, sV + (kk*16)*136 + wn2 + j*16, 136);
                    wmma::mma_sync(oc[j], pf, vf, oc[j]);
                }
            }
            #pragma unroll
            for (int j = 0; j < 4; j++)
                wmma::store_matrix_sync(sO + wm*132 + wn2 + j*16, oc[j], 132, wmma::mem_row_major);
        }
        __syncthreads();
    }

    // epilogue: normalize, merge heads, single fp16 output
    for (int v = tid; v < 64*128; v += 256) {
        int r = v >> 7, d = v & 127;
        float o = sO[r*132 + d] / sl[r];
        size_t dst = ((size_t)b * SEQ + q0 + r) * HID + (size_t)h * HDIM + d;
        g_AO[dst] = __float2half(o);
    }
}

// ---------------- launch ----------------
extern "C" void kernel_launch(void* const* d_in, const int* in_sizes, int n_in,
                              void* d_out, int out_size) {
    const float* X    = (const float*)d_in[0];
    const float* Wqkv = (const float*)d_in[1];
    const float* Wo   = (const float*)d_in[2];

    cudaFuncSetAttribute(flash_kernel, cudaFuncAttributeMaxDynamicSharedMemorySize, FL_SMEM);
    cudaFuncSetAttribute(gemm_qkv_merged_kernel, cudaFuncAttributeMaxDynamicSharedMemorySize, GEMM_SMEM);
    cudaFuncSetAttribute(gemm_out_kernel, cudaFuncAttributeMaxDynamicSharedMemorySize, GEMM_SMEM);

    __half *Xhi, *Wqh, *Wql, *Woh, *AO;
    cudaGetSymbolAddress((void**)&Xhi, g_Xhi);
    cudaGetSymbolAddress((void**)&Wqh, g_Wqkvhi);
    cudaGetSymbolAddress((void**)&Wql, g_Wqkvlo);
    cudaGetSymbolAddress((void**)&Woh, g_Wohi);
    cudaGetSymbolAddress((void**)&AO,  g_AO);

    conv_x_kernel    <<<(MROWS*HID + 255)/256, 256>>>(X);
    split_wqkv_kernel<<<(QKVN*HID  + 255)/256, 256>>>(Wqkv);
    conv_wo_kernel   <<<(HID*HID   + 255)/256, 256>>>(Wo);
    rope_table_kernel<<<(SEQ*64    + 255)/256, 256>>>();

    // full QKV projection in one launch (M=4096, N=12288)
    gemm_qkv_merged_kernel<<<(MROWS/128)*(QKVN/128), 256, GEMM_SMEM>>>(
        Xhi, Wqh, Wql, HID, MROWS/128, QKVN/128);

    flash_kernel<<<dim3(SEQ/64, NHEAD, BATCH), 256, FL_SMEM>>>();

    // Output projection (N=4096): pure fp16
    gemm_out_kernel<<<(MROWS/128)*(HID/128), 256, GEMM_SMEM>>>(
        AO, Woh, (float*)d_out, HID, HID, MROWS/128, HID/128);
}

// round 14
// speedup vs baseline: 5.7224x; 1.0716x over previous
#include <cuda_runtime.h>
#include <cuda_fp16.h>
#include <mma.h>
#include <math.h>
#include <stdint.h>

using namespace nvcuda;

#define BATCH 2
#define SEQ   2048
#define HID   4096
#define NHEAD 32
#define HDIM  128
#define MROWS (BATCH*SEQ)     /* 4096 */
#define QKVN  (3*HID)         /* 12288 */

// ---------------- scratch ----------------
__device__ __half g_Xhi   [MROWS*HID];
__device__ __half g_Wqkvhi[QKVN*HID];
__device__ __half g_Wqkvlo[QKVN*HID];
__device__ __half g_Wohi  [HID*HID];
__device__ __half g_Qhi   [MROWS*HID];
__device__ __half g_Khi   [MROWS*HID];
__device__ __half g_V     [MROWS*HID];
__device__ __half g_AO    [MROWS*HID];
__device__ float  g_cos   [SEQ*64];
__device__ float  g_sin   [SEQ*64];

__device__ __forceinline__ void splitf(float x, __half &hi, __half &lo) {
    hi = __float2half(x);
    lo = __float2half(x - __half2float(hi));
}

// ---------------- cp.async helpers ----------------
static __device__ __forceinline__ uint32_t smem_u32(const void* p) {
    uint32_t a;
    asm("{ .reg .u64 t; cvta.to.shared.u64 t, %1; cvt.u32.u64 %0, t; }" : "=r"(a) : "l"(p));
    return a;
}
static __device__ __forceinline__ void cp_async16(uint32_t dst, const void* src) {
    asm volatile("cp.async.cg.shared.global [%0], [%1], 16;\n" :: "r"(dst), "l"(src));
}
#define CP_COMMIT() asm volatile("cp.async.commit_group;\n" ::: "memory")
#define CP_WAIT1()  asm volatile("cp.async.wait_group 1;\n" ::: "memory")

// ---------------- elementwise kernels ----------------
__global__ void __launch_bounds__(256) conv_x_kernel(const float* __restrict__ src) {
    int idx = blockIdx.x * blockDim.x + threadIdx.x;
    if (idx < MROWS*HID) g_Xhi[idx] = __float2half(src[idx]);
}
__global__ void __launch_bounds__(256) split_wqkv_kernel(const float* __restrict__ src) {
    int idx = blockIdx.x * blockDim.x + threadIdx.x;
    if (idx < QKVN*HID) {
        float x = src[idx];
        __half h, l; splitf(x, h, l);
        g_Wqkvhi[idx] = h; g_Wqkvlo[idx] = l;
    }
}
__global__ void __launch_bounds__(256) conv_wo_kernel(const float* __restrict__ src) {
    int idx = blockIdx.x * blockDim.x + threadIdx.x;
    if (idx < HID*HID) g_Wohi[idx] = __float2half(src[idx]);
}

// ---------------- RoPE cos/sin table ----------------
__global__ void __launch_bounds__(256) rope_table_kernel() {
    int idx = blockIdx.x * blockDim.x + threadIdx.x;
    if (idx >= SEQ*64) return;
    int i = idx & 63;
    int s = idx >> 6;
    double inv = pow(10000.0, -((double)(2*i)) / 128.0);
    float invf = (float)inv;
    float ang  = (float)s * invf;
    g_cos[idx] = (float)cos((double)ang);
    g_sin[idx] = (float)sin((double)ang);
}

// =====================================================================
//  Pipelined fp16 GEMM: CTA 128x128, 256 threads, warp 64x32.
//  KC=32, 2-stage cp.async, 2 CTAs/SM.
//  BTERMS=2: A·Bhi + A·Blo ; BTERMS=1: A·Bhi.
//  EPI: 0 = fp32 C direct ; 1 = fused RoPE+transpose fp16 (Q/K) ;
//       2 = direct fp16 V transpose.
// =====================================================================

#define KC        32
#define ARR_HALF  (128*40)                 /* 32 data halves + 8 pad */
#define STAGE_HALF (4*ARR_HALF)            /* 20480 */
#define STAGE_BYTES (STAGE_HALF*2)         /* 40960 */
#define GEMM_SMEM (2*STAGE_BYTES)          /* 81920 -> 2 CTAs/SM */

template<int BTERMS>
static __device__ __forceinline__ void gemm_load_stage(
    uint32_t stage_base, int tid,
    const __half* __restrict__ Ahi,
    const __half* __restrict__ Bhi, const __half* __restrict__ Blo,
    int bm, int bn, int K, int k0)
{
    int chunk = tid & 3;        // 16B chunk within 64B data row
    int r0    = tid >> 2;       // 0..63
    const char* gAh = (const char*)(Ahi + (size_t)bm * K + k0) + chunk * 16;
    const char* gBh = (const char*)(Bhi + (size_t)bn * K + k0) + chunk * 16;
    const char* gBl = (const char*)(Blo + (size_t)bn * K + k0) + chunk * 16;
    #pragma unroll
    for (int u = 0; u < 2; u++) {
        int row = r0 + u * 64;
        uint32_t so = (uint32_t)(row * 80 + chunk * 16);
        cp_async16(stage_base + so,              gAh + (size_t)row * K * 2);
        cp_async16(stage_base + 4*ARR_HALF + so, gBh + (size_t)row * K * 2);
        if (BTERMS == 2)
            cp_async16(stage_base + 6*ARR_HALF + so, gBl + (size_t)row * K * 2);
    }
}

template<int BTERMS, int EPI>
static __device__ __forceinline__ void gemm_body(
    __half* smh, uint32_t smem_base, int tid, int wid,
    const __half* __restrict__ Ahi,
    const __half* __restrict__ Bhi, const __half* __restrict__ Blo,
    float* __restrict__ C, int K, int ldc, int bm, int bn)
{
    int wm = (wid >> 2) * 64;   // 2 warp rows of 64
    int wn = (wid & 3) * 32;    // 4 warp cols of 32

    wmma::fragment<wmma::accumulator,16,16,16,float> acc[4][2];
    #pragma unroll
    for (int i = 0; i < 4; i++)
        #pragma unroll
        for (int j = 0; j < 2; j++)
            wmma::fill_fragment(acc[i][j], 0.0f);

    const int NIT = K / KC;

    gemm_load_stage<BTERMS>(smem_base,               tid, Ahi, Bhi, Blo, bm, bn, K, 0);
    CP_COMMIT();
    gemm_load_stage<BTERMS>(smem_base + STAGE_BYTES, tid, Ahi, Bhi, Blo, bm, bn, K, KC);
    CP_COMMIT();

    for (int it = 0; it < NIT; it++) {
        CP_WAIT1();
        __syncthreads();

        const __half* st  = smh + (size_t)(it & 1) * STAGE_HALF;
        const __half* sAh = st;
        const __half* sBh = st + 2*ARR_HALF;
        const __half* sBl = st + 3*ARR_HALF;

        #pragma unroll
        for (int kk = 0; kk < 2; kk++) {
            wmma::fragment<wmma::matrix_b,16,16,16,__half,wmma::col_major> bh[2], bl[2];
            #pragma unroll
            for (int j = 0; j < 2; j++) {
                wmma::load_matrix_sync(bh[j], sBh + (wn + j*16)*40 + kk*16, 40);
                if (BTERMS == 2)
                    wmma::load_matrix_sync(bl[j], sBl + (wn + j*16)*40 + kk*16, 40);
            }
            #pragma unroll
            for (int i = 0; i < 4; i++) {
                wmma::fragment<wmma::matrix_a,16,16,16,__half,wmma::row_major> ah;
                wmma::load_matrix_sync(ah, sAh + (wm + i*16)*40 + kk*16, 40);
                #pragma unroll
                for (int j = 0; j < 2; j++) {
                    wmma::mma_sync(acc[i][j], ah, bh[j], acc[i][j]);
                    if (BTERMS == 2)
                        wmma::mma_sync(acc[i][j], ah, bl[j], acc[i][j]);
                }
            }
        }
        __syncthreads();

        int nxt = it + 2;
        if (nxt < NIT)
            gemm_load_stage<BTERMS>(smem_base + (uint32_t)(nxt & 1) * STAGE_BYTES, tid,
                                    Ahi, Bhi, Blo, bm, bn, K, nxt * KC);
        CP_COMMIT();
    }

    if (EPI == 0) {
        #pragma unroll
        for (int i = 0; i < 4; i++)
            #pragma unroll
            for (int j = 0; j < 2; j++) {
                size_t off = (size_t)(bm + wm + i*16) * ldc + bn + wn + j*16;
                wmma::store_matrix_sync(&C[off], acc[i][j], ldc, wmma::mem_row_major);
            }
        return;
    }

    // stage C tile (128 x 128, stride 132) in smem for fused epilogue
    float* sC = (float*)smh;
    #pragma unroll
    for (int i = 0; i < 4; i++)
        #pragma unroll
        for (int j = 0; j < 2; j++)
            wmma::store_matrix_sync(sC + (wm + i*16)*132 + wn + j*16, acc[i][j],
                                    132, wmma::mem_row_major);
    __syncthreads();

    int h = (bn >> 7) & 31;
    if (EPI == 1) {
        __half* D = (bn >= HID) ? g_Khi : g_Qhi;
        for (int idx = tid; idx < 128*64; idx += 256) {
            int r = idx >> 6, d = idx & 63;
            float x1 = sC[r*132 + d];
            float x2 = sC[r*132 + d + 64];
            int row = bm + r;
            int s   = row & (SEQ-1);
            int b   = row >> 11;
            float c  = g_cos[s*64 + d];
            float sn = g_sin[s*64 + d];
            size_t dst = (((size_t)b * NHEAD + h) * SEQ + s) * HDIM + d;
            D[dst]    = __float2half(x1*c - x2*sn);
            D[dst+64] = __float2half(x1*sn + x2*c);
        }
    } else {
        for (int idx = tid; idx < 128*128; idx += 256) {
            int r = idx >> 7, d = idx & 127;
            int row = bm + r;
            int s   = row & (SEQ-1);
            int b   = row >> 11;
            g_V[(((size_t)b * NHEAD + h) * SEQ + s) * HDIM + d] = __float2half(sC[r*132 + d]);
        }
    }
}

// merged QKV projection:
//   Q cols [0,HID):      1-Bterm + RoPE epi  (fp16 weights)
//   K cols [HID,2*HID):  2-Bterm + RoPE epi  (hi/lo weights)
//   V cols [2*HID,3*HID):1-Bterm + fp16 transpose epi
__global__ void __launch_bounds__(256, 2) gemm_qkv_merged_kernel(
    const __half* __restrict__ Ahi,
    const __half* __restrict__ Bhi, const __half* __restrict__ Blo,
    int K, int grid_m, int grid_n)
{
    extern __shared__ __half smh[];
    uint32_t smem_base = smem_u32(smh);
    int tid = threadIdx.x;
    int wid = tid >> 5;

    int pid = blockIdx.x;
    const int GRPW = 16;
    int width = GRPW * grid_n;
    int g   = pid / width;
    int rem = pid - g * width;
    int gm  = grid_m - g * GRPW; if (gm > GRPW) gm = GRPW;
    int bm  = (g * GRPW + (rem % gm)) * 128;
    int bn  = (rem / gm) * 128;

    if (bn < HID)
        gemm_body<1,1>(smh, smem_base, tid, wid, Ahi, Bhi, Blo, nullptr, K, 0, bm, bn);
    else if (bn < 2*HID)
        gemm_body<2,1>(smh, smem_base, tid, wid, Ahi, Bhi, Blo, nullptr, K, 0, bm, bn);
    else
        gemm_body<1,2>(smh, smem_base, tid, wid, Ahi, Bhi, Blo, nullptr, K, 0, bm, bn);
}

// out projection: pure fp16, fp32 epilogue
__global__ void __launch_bounds__(256, 2) gemm_out_kernel(
    const __half* __restrict__ Ahi, const __half* __restrict__ Bhi,
    float* __restrict__ C, int K, int ldc, int grid_m, int grid_n)
{
    extern __shared__ __half smh[];
    uint32_t smem_base = smem_u32(smh);
    int tid = threadIdx.x;
    int wid = tid >> 5;

    int pid = blockIdx.x;
    const int GRPW = 16;
    int width = GRPW * grid_n;
    int g   = pid / width;
    int rem = pid - g * width;
    int gm  = grid_m - g * GRPW; if (gm > GRPW) gm = GRPW;
    int bm  = (g * GRPW + (rem % gm)) * 128;
    int bn  = (rem / gm) * 128;

    gemm_body<1,0>(smh, smem_base, tid, wid, Ahi, Bhi, Bhi, C, K, ldc, bm, bn);
}

// ---------------- flash attention: pure fp16 Q/K/V, fp32 accum, causal ----------------
#define TILE_H   (64*136)
#define TILE_B   (TILE_H*2)
#define FL_SMEM  (5*TILE_B + 64*68*4 + 64*72*2 + 64*132*4 + 3*64*4)

static __device__ __forceinline__ void flash_issue_tile(
    uint32_t dKh, uint32_t dV,
    const __half* __restrict__ Kh, const __half* __restrict__ V, int tid)
{
    int chunk = tid & 15;
    int r0    = tid >> 4;
    #pragma unroll
    for (int u = 0; u < 4; u++) {
        int r = r0 + u * 16;
        uint32_t so = (uint32_t)(r * 272 + chunk * 16);
        size_t   go = (size_t)r * HDIM * 2 + chunk * 16;
        cp_async16(dKh + so, (const char*)Kh + go);
        cp_async16(dV  + so, (const char*)V  + go);
    }
}

__global__ void __launch_bounds__(256) flash_kernel() {
    extern __shared__ unsigned char smraw[];
    __half* sQh = (__half*)smraw;
    __half* sKB = sQh + TILE_H;              // 2 buffers x (Kh, V)
    float*  sS  = (float*)(sKB + 4*TILE_H);
    __half* sP  = (__half*)(sS + 64*68);
    float*  sO  = (float*)(sP + 64*72);
    float*  smx = sO + 64*132;
    float*  sl  = smx + 64;

    int tid = threadIdx.x;
    int wid = tid >> 5;
    int qt  = gridDim.x - 1 - blockIdx.x;   // longest CTAs first
    int h   = blockIdx.y;
    int b   = blockIdx.z;
    int bh  = b * NHEAD + h;
    int q0  = qt * 64;

    const float scale = 0.08838834764831845f;

    const __half* Khg = g_Khi + (size_t)bh * SEQ * HDIM;
    const __half* Vg  = g_V   + (size_t)bh * SEQ * HDIM;

    uint32_t sKB_u = smem_u32(sKB);

    flash_issue_tile(sKB_u, sKB_u + TILE_B, Khg, Vg, tid);
    CP_COMMIT();

    {
        const __half* Qh = g_Qhi + ((size_t)bh * SEQ + q0) * HDIM;
        for (int v = tid; v < 1024; v += 256) {
            int r = v >> 4, c = (v & 15) << 3;
            *(int4*)(sQh + r*136 + c) = *(const int4*)(Qh + r*HDIM + c);
        }
    }
    for (int v = tid; v < 64*132; v += 256) sO[v] = 0.0f;
    if (tid < 64) { smx[tid] = -INFINITY; sl[tid] = 0.0f; }

    int wm = (wid >> 1) * 16;

    for (int kt = 0; kt <= qt; kt++) {
        if (kt + 1 <= qt) {
            uint32_t nb = sKB_u + (uint32_t)((kt + 1) & 1) * 2 * TILE_B;
            flash_issue_tile(nb, nb + TILE_B,
                             Khg + (size_t)(kt+1)*64*HDIM,
                             Vg  + (size_t)(kt+1)*64*HDIM, tid);
        }
        CP_COMMIT();
        CP_WAIT1();
        __syncthreads();

        __half* sKh = sKB + (size_t)(kt & 1) * 2 * TILE_H;
        __half* sV  = sKh + TILE_H;

        // S = Q K^T (pure fp16 inputs, fp32 accum)
        {
            int wn = (wid & 1) * 32;
            wmma::fragment<wmma::accumulator,16,16,16,float> sacc[2];
            wmma::fill_fragment(sacc[0], 0.0f);
            wmma::fill_fragment(sacc[1], 0.0f);
            #pragma unroll
            for (int d8 = 0; d8 < 8; d8++) {
                wmma::fragment<wmma::matrix_a,16,16,16,__half,wmma::row_major> ah;
                wmma::load_matrix_sync(ah, sQh + wm*136 + d8*16, 136);
                #pragma unroll
                for (int j = 0; j < 2; j++) {
                    wmma::fragment<wmma::matrix_b,16,16,16,__half,wmma::col_major> kh;
                    wmma::load_matrix_sync(kh, sKh + (wn + j*16)*136 + d8*16, 136);
                    wmma::mma_sync(sacc[j], ah, kh, sacc[j]);
                }
            }
            wmma::store_matrix_sync(sS + wm*68 + wn,      sacc[0], 68, wmma::mem_row_major);
            wmma::store_matrix_sync(sS + wm*68 + wn + 16, sacc[1], 68, wmma::mem_row_major);
        }
        __syncthreads();

        // online softmax + fused O rescale (4 threads per row)
        {
            int r    = tid >> 2;
            int lane = tid & 3;
            bool diag = (kt == qt);
            int jmax = diag ? (r + 1) : 64;

            float lm = -INFINITY;
            #pragma unroll
            for (int jj = 0; jj < 16; jj++) {
                int j = lane*16 + jj;
                if (j < jmax) lm = fmaxf(lm, sS[r*68 + j] * scale);
            }
            lm = fmaxf(lm, __shfl_xor_sync(0xffffffffu, lm, 1));
            lm = fmaxf(lm, __shfl_xor_sync(0xffffffffu, lm, 2));
            float mo = smx[r];
            float mn = fmaxf(mo, lm);

            float rl = 0.0f;
            #pragma unroll
            for (int jj = 0; jj < 16; jj++) {
                int j = lane*16 + jj;
                float p = 0.0f;
                if (j < jmax) { p = __expf(sS[r*68 + j] * scale - mn); rl += p; }
                sP[r*72 + j] = __float2half(p);
            }
            rl += __shfl_xor_sync(0xffffffffu, rl, 1);
            rl += __shfl_xor_sync(0xffffffffu, rl, 2);

            float a = __expf(mo - mn);
            if (lane == 0) {
                smx[r] = mn;
                sl[r]  = sl[r] * a + rl;
            }
            #pragma unroll
            for (int dd = 0; dd < 32; dd++)
                sO[r*132 + lane*32 + dd] *= a;
        }
        __syncthreads();

        // O += P @ V
        {
            int wn2 = (wid & 1) * 64;
            wmma::fragment<wmma::accumulator,16,16,16,float> oc[4];
            #pragma unroll
            for (int j = 0; j < 4; j++)
                wmma::load_matrix_sync(oc[j], sO + wm*132 + wn2 + j*16, 132, wmma::mem_row_major);
            #pragma unroll
            for (int kk = 0; kk < 4; kk++) {
                wmma::fragment<wmma::matrix_a,16,16,16,__half,wmma::row_major> pf;
                wmma::load_matrix_sync(pf, sP + wm*72 + kk*16, 72);
                #pragma unroll
                for (int j = 0; j < 4; j++) {
                    wmma::fragment<wmma::matrix_b,16,16,16,__half,wmma::row_major> vf;
                    wmma::load_matrix_sync(vf, sV + (kk*16)*136 + wn2 + j*16, 136);
                    wmma::mma_sync(oc[j], pf, vf, oc[j]);
                }
            }
            #pragma unroll
            for (int j = 0; j < 4; j++)
                wmma::store_matrix_sync(sO + wm*132 + wn2 + j*16, oc[j], 132, wmma::mem_row_major);
        }
        __syncthreads();
    }

    // epilogue: normalize, merge heads, single fp16 output
    for (int v = tid; v < 64*128; v += 256) {
        int r = v >> 7, d = v & 127;
        float o = sO[r*132 + d] / sl[r];
        size_t dst = ((size_t)b * SEQ + q0 + r) * HID + (size_t)h * HDIM + d;
        g_AO[dst] = __float2half(o);
    }
}

// ---------------- launch ----------------
extern "C" void kernel_launch(void* const* d_in, const int* in_sizes, int n_in,
                              void* d_out, int out_size) {
    const float* X    = (const float*)d_in[0];
    const float* Wqkv = (const float*)d_in[1];
    const float* Wo   = (const float*)d_in[2];

    cudaFuncSetAttribute(flash_kernel, cudaFuncAttributeMaxDynamicSharedMemorySize, FL_SMEM);
    cudaFuncSetAttribute(gemm_qkv_merged_kernel, cudaFuncAttributeMaxDynamicSharedMemorySize, GEMM_SMEM);
    cudaFuncSetAttribute(gemm_out_kernel, cudaFuncAttributeMaxDynamicSharedMemorySize, GEMM_SMEM);

    __half *Xhi, *Wqh, *Wql, *Woh, *AO;
    cudaGetSymbolAddress((void**)&Xhi, g_Xhi);
    cudaGetSymbolAddress((void**)&Wqh, g_Wqkvhi);
    cudaGetSymbolAddress((void**)&Wql, g_Wqkvlo);
    cudaGetSymbolAddress((void**)&Woh, g_Wohi);
    cudaGetSymbolAddress((void**)&AO,  g_AO);

    conv_x_kernel    <<<(MROWS*HID + 255)/256, 256>>>(X);
    split_wqkv_kernel<<<(QKVN*HID  + 255)/256, 256>>>(Wqkv);
    conv_wo_kernel   <<<(HID*HID   + 255)/256, 256>>>(Wo);
    rope_table_kernel<<<(SEQ*64    + 255)/256, 256>>>();

    // full QKV projection in one launch (M=4096, N=12288)
    gemm_qkv_merged_kernel<<<(MROWS/128)*(QKVN/128), 256, GEMM_SMEM>>>(
        Xhi, Wqh, Wql, HID, MROWS/128, QKVN/128);

    flash_kernel<<<dim3(SEQ/64, NHEAD, BATCH), 256, FL_SMEM>>>();

    // Output projection (N=4096): pure fp16
    gemm_out_kernel<<<(MROWS/128)*(HID/128), 256, GEMM_SMEM>>>(
        AO, Woh, (float*)d_out, HID, HID, MROWS/128, HID/128);
}

// round 15
// speedup vs baseline: 6.2493x; 1.0921x over previous
#include <cuda_runtime.h>
#include <cuda_fp16.h>
#include <mma.h>
#include <math.h>
#include <stdint.h>

using namespace nvcuda;

#define BATCH 2
#define SEQ   2048
#define HID   4096
#define NHEAD 32
#define HDIM  128
#define MROWS (BATCH*SEQ)     /* 4096 */
#define QKVN  (3*HID)         /* 12288 */

// ---------------- scratch ----------------
__device__ __half g_Xhi   [MROWS*HID];
__device__ __half g_Wqkvhi[QKVN*HID];
__device__ __half g_Wohi  [HID*HID];
__device__ __half g_Qhi   [MROWS*HID];
__device__ __half g_Khi   [MROWS*HID];
__device__ __half g_V     [MROWS*HID];
__device__ __half g_AO    [MROWS*HID];
__device__ float  g_cos   [SEQ*64];
__device__ float  g_sin   [SEQ*64];

// ---------------- cp.async helpers ----------------
static __device__ __forceinline__ uint32_t smem_u32(const void* p) {
    uint32_t a;
    asm("{ .reg .u64 t; cvta.to.shared.u64 t, %1; cvt.u32.u64 %0, t; }" : "=r"(a) : "l"(p));
    return a;
}
static __device__ __forceinline__ void cp_async16(uint32_t dst, const void* src) {
    asm volatile("cp.async.cg.shared.global [%0], [%1], 16;\n" :: "r"(dst), "l"(src));
}
#define CP_COMMIT() asm volatile("cp.async.commit_group;\n" ::: "memory")
#define CP_WAIT1()  asm volatile("cp.async.wait_group 1;\n" ::: "memory")

// ---------------- elementwise kernels ----------------
__global__ void __launch_bounds__(256) conv_x_kernel(const float* __restrict__ src) {
    int idx = blockIdx.x * blockDim.x + threadIdx.x;
    if (idx < MROWS*HID) g_Xhi[idx] = __float2half(src[idx]);
}
__global__ void __launch_bounds__(256) conv_wqkv_kernel(const float* __restrict__ src) {
    int idx = blockIdx.x * blockDim.x + threadIdx.x;
    if (idx < QKVN*HID) g_Wqkvhi[idx] = __float2half(src[idx]);
}
__global__ void __launch_bounds__(256) conv_wo_kernel(const float* __restrict__ src) {
    int idx = blockIdx.x * blockDim.x + threadIdx.x;
    if (idx < HID*HID) g_Wohi[idx] = __float2half(src[idx]);
}

// ---------------- RoPE cos/sin table ----------------
__global__ void __launch_bounds__(256) rope_table_kernel() {
    int idx = blockIdx.x * blockDim.x + threadIdx.x;
    if (idx >= SEQ*64) return;
    int i = idx & 63;
    int s = idx >> 6;
    double inv = pow(10000.0, -((double)(2*i)) / 128.0);
    float invf = (float)inv;
    float ang  = (float)s * invf;
    g_cos[idx] = (float)cos((double)ang);
    g_sin[idx] = (float)sin((double)ang);
}

// =====================================================================
//  Pipelined fp16 GEMM: CTA 128x128, 256 threads, warp 64x32.
//  KC=32, 2-stage cp.async, pure fp16 A·B.
//  EPI: 0 = fp32 C direct ; 1 = fused RoPE+transpose fp16 (Q/K) ;
//       2 = direct fp16 V transpose.
// =====================================================================

#define KC        32
#define ARR_HALF  (128*40)                 /* 32 data halves + 8 pad */
#define STAGE_HALF (2*ARR_HALF)            /* 10240: A + B */
#define STAGE_BYTES (STAGE_HALF*2)         /* 20480 */
#define GEMM_SMEM (2*STAGE_BYTES + 128*132*4) /* stages + epilogue C tile: 108KB */

static __device__ __forceinline__ void gemm_load_stage(
    uint32_t stage_base, int tid,
    const __half* __restrict__ A, const __half* __restrict__ B,
    int bm, int bn, int K, int k0)
{
    int chunk = tid & 3;        // 16B chunk within 64B data row
    int r0    = tid >> 2;       // 0..63
    const char* gA = (const char*)(A + (size_t)bm * K + k0) + chunk * 16;
    const char* gB = (const char*)(B + (size_t)bn * K + k0) + chunk * 16;
    #pragma unroll
    for (int u = 0; u < 2; u++) {
        int row = r0 + u * 64;
        uint32_t so = (uint32_t)(row * 80 + chunk * 16);
        cp_async16(stage_base + so,              gA + (size_t)row * K * 2);
        cp_async16(stage_base + 2*ARR_HALF + so, gB + (size_t)row * K * 2);
    }
}

template<int EPI>
static __device__ __forceinline__ void gemm_body(
    __half* smh, uint32_t smem_base, int tid, int wid,
    const __half* __restrict__ A, const __half* __restrict__ B,
    float* __restrict__ C, int K, int ldc, int bm, int bn)
{
    int wm = (wid >> 2) * 64;   // 2 warp rows of 64
    int wn = (wid & 3) * 32;    // 4 warp cols of 32

    wmma::fragment<wmma::accumulator,16,16,16,float> acc[4][2];
    #pragma unroll
    for (int i = 0; i < 4; i++)
        #pragma unroll
        for (int j = 0; j < 2; j++)
            wmma::fill_fragment(acc[i][j], 0.0f);

    const int NIT = K / KC;

    gemm_load_stage(smem_base,               tid, A, B, bm, bn, K, 0);
    CP_COMMIT();
    gemm_load_stage(smem_base + STAGE_BYTES, tid, A, B, bm, bn, K, KC);
    CP_COMMIT();

    for (int it = 0; it < NIT; it++) {
        CP_WAIT1();
        __syncthreads();

        const __half* st = smh + (size_t)(it & 1) * STAGE_HALF;
        const __half* sA = st;
        const __half* sB = st + ARR_HALF;

        #pragma unroll
        for (int kk = 0; kk < 2; kk++) {
            wmma::fragment<wmma::matrix_b,16,16,16,__half,wmma::col_major> bf[2];
            #pragma unroll
            for (int j = 0; j < 2; j++)
                wmma::load_matrix_sync(bf[j], sB + (wn + j*16)*40 + kk*16, 40);
            #pragma unroll
            for (int i = 0; i < 4; i++) {
                wmma::fragment<wmma::matrix_a,16,16,16,__half,wmma::row_major> af;
                wmma::load_matrix_sync(af, sA + (wm + i*16)*40 + kk*16, 40);
                #pragma unroll
                for (int j = 0; j < 2; j++)
                    wmma::mma_sync(acc[i][j], af, bf[j], acc[i][j]);
            }
        }
        __syncthreads();

        int nxt = it + 2;
        if (nxt < NIT)
            gemm_load_stage(smem_base + (uint32_t)(nxt & 1) * STAGE_BYTES, tid,
                            A, B, bm, bn, K, nxt * KC);
        CP_COMMIT();
    }

    if (EPI == 0) {
        #pragma unroll
        for (int i = 0; i < 4; i++)
            #pragma unroll
            for (int j = 0; j < 2; j++) {
                size_t off = (size_t)(bm + wm + i*16) * ldc + bn + wn + j*16;
                wmma::store_matrix_sync(&C[off], acc[i][j], ldc, wmma::mem_row_major);
            }
        return;
    }

    // stage C tile (128 x 128, stride 132) in smem (after the stage buffers)
    float* sC = (float*)(smh + 2*STAGE_HALF);
    #pragma unroll
    for (int i = 0; i < 4; i++)
        #pragma unroll
        for (int j = 0; j < 2; j++)
            wmma::store_matrix_sync(sC + (wm + i*16)*132 + wn + j*16, acc[i][j],
                                    132, wmma::mem_row_major);
    __syncthreads();

    int h = (bn >> 7) & 31;
    if (EPI == 1) {
        __half* D = (bn >= HID) ? g_Khi : g_Qhi;
        for (int idx = tid; idx < 128*64; idx += 256) {
            int r = idx >> 6, d = idx & 63;
            float x1 = sC[r*132 + d];
            float x2 = sC[r*132 + d + 64];
            int row = bm + r;
            int s   = row & (SEQ-1);
            int b   = row >> 11;
            float c  = g_cos[s*64 + d];
            float sn = g_sin[s*64 + d];
            size_t dst = (((size_t)b * NHEAD + h) * SEQ + s) * HDIM + d;
            D[dst]    = __float2half(x1*c - x2*sn);
            D[dst+64] = __float2half(x1*sn + x2*c);
        }
    } else {
        for (int idx = tid; idx < 128*128; idx += 256) {
            int r = idx >> 7, d = idx & 127;
            int row = bm + r;
            int s   = row & (SEQ-1);
            int b   = row >> 11;
            g_V[(((size_t)b * NHEAD + h) * SEQ + s) * HDIM + d] = __float2half(sC[r*132 + d]);
        }
    }
}

// merged QKV projection: pure fp16 everywhere; Q/K cols RoPE epi, V cols fp16 epi
__global__ void __launch_bounds__(256, 2) gemm_qkv_merged_kernel(
    const __half* __restrict__ A, const __half* __restrict__ B,
    int K, int grid_m, int grid_n)
{
    extern __shared__ __half smh[];
    uint32_t smem_base = smem_u32(smh);
    int tid = threadIdx.x;
    int wid = tid >> 5;

    int pid = blockIdx.x;
    const int GRPW = 16;
    int width = GRPW * grid_n;
    int g   = pid / width;
    int rem = pid - g * width;
    int gm  = grid_m - g * GRPW; if (gm > GRPW) gm = GRPW;
    int bm  = (g * GRPW + (rem % gm)) * 128;
    int bn  = (rem / gm) * 128;

    if (bn < 2*HID)
        gemm_body<1>(smh, smem_base, tid, wid, A, B, nullptr, K, 0, bm, bn);
    else
        gemm_body<2>(smh, smem_base, tid, wid, A, B, nullptr, K, 0, bm, bn);
}

// out projection: pure fp16, fp32 epilogue
__global__ void __launch_bounds__(256, 2) gemm_out_kernel(
    const __half* __restrict__ A, const __half* __restrict__ B,
    float* __restrict__ C, int K, int ldc, int grid_m, int grid_n)
{
    extern __shared__ __half smh[];
    uint32_t smem_base = smem_u32(smh);
    int tid = threadIdx.x;
    int wid = tid >> 5;

    int pid = blockIdx.x;
    const int GRPW = 16;
    int width = GRPW * grid_n;
    int g   = pid / width;
    int rem = pid - g * width;
    int gm  = grid_m - g * GRPW; if (gm > GRPW) gm = GRPW;
    int bm  = (g * GRPW + (rem % gm)) * 128;
    int bn  = (rem / gm) * 128;

    gemm_body<0>(smh, smem_base, tid, wid, A, B, C, K, ldc, bm, bn);
}

// ---------------- flash attention: pure fp16 Q/K/V, fp32 accum, causal ----------------
#define TILE_H   (64*136)
#define TILE_B   (TILE_H*2)
#define FL_SMEM  (5*TILE_B + 64*68*4 + 64*72*2 + 64*132*4 + 3*64*4)

static __device__ __forceinline__ void flash_issue_tile(
    uint32_t dKh, uint32_t dV,
    const __half* __restrict__ Kh, const __half* __restrict__ V, int tid)
{
    int chunk = tid & 15;
    int r0    = tid >> 4;
    #pragma unroll
    for (int u = 0; u < 4; u++) {
        int r = r0 + u * 16;
        uint32_t so = (uint32_t)(r * 272 + chunk * 16);
        size_t   go = (size_t)r * HDIM * 2 + chunk * 16;
        cp_async16(dKh + so, (const char*)Kh + go);
        cp_async16(dV  + so, (const char*)V  + go);
    }
}

__global__ void __launch_bounds__(256) flash_kernel() {
    extern __shared__ unsigned char smraw[];
    __half* sQh = (__half*)smraw;
    __half* sKB = sQh + TILE_H;              // 2 buffers x (Kh, V)
    float*  sS  = (float*)(sKB + 4*TILE_H);
    __half* sP  = (__half*)(sS + 64*68);
    float*  sO  = (float*)(sP + 64*72);
    float*  smx = sO + 64*132;
    float*  sl  = smx + 64;

    int tid = threadIdx.x;
    int wid = tid >> 5;
    int qt  = gridDim.x - 1 - blockIdx.x;   // longest CTAs first
    int h   = blockIdx.y;
    int b   = blockIdx.z;
    int bh  = b * NHEAD + h;
    int q0  = qt * 64;

    const float scale = 0.08838834764831845f;

    const __half* Khg = g_Khi + (size_t)bh * SEQ * HDIM;
    const __half* Vg  = g_V   + (size_t)bh * SEQ * HDIM;

    uint32_t sKB_u = smem_u32(sKB);

    flash_issue_tile(sKB_u, sKB_u + TILE_B, Khg, Vg, tid);
    CP_COMMIT();

    {
        const __half* Qh = g_Qhi + ((size_t)bh * SEQ + q0) * HDIM;
        for (int v = tid; v < 1024; v += 256) {
            int r = v >> 4, c = (v & 15) << 3;
            *(int4*)(sQh + r*136 + c) = *(const int4*)(Qh + r*HDIM + c);
        }
    }
    for (int v = tid; v < 64*132; v += 256) sO[v] = 0.0f;
    if (tid < 64) { smx[tid] = -INFINITY; sl[tid] = 0.0f; }

    int wm = (wid >> 1) * 16;

    for (int kt = 0; kt <= qt; kt++) {
        if (kt + 1 <= qt) {
            uint32_t nb = sKB_u + (uint32_t)((kt + 1) & 1) * 2 * TILE_B;
            flash_issue_tile(nb, nb + TILE_B,
                             Khg + (size_t)(kt+1)*64*HDIM,
                             Vg  + (size_t)(kt+1)*64*HDIM, tid);
        }
        CP_COMMIT();
        CP_WAIT1();
        __syncthreads();

        __half* sKh = sKB + (size_t)(kt & 1) * 2 * TILE_H;
        __half* sV  = sKh + TILE_H;

        // S = Q K^T (pure fp16 inputs, fp32 accum)
        {
            int wn = (wid & 1) * 32;
            wmma::fragment<wmma::accumulator,16,16,16,float> sacc[2];
            wmma::fill_fragment(sacc[0], 0.0f);
            wmma::fill_fragment(sacc[1], 0.0f);
            #pragma unroll
            for (int d8 = 0; d8 < 8; d8++) {
                wmma::fragment<wmma::matrix_a,16,16,16,__half,wmma::row_major> ah;
                wmma::load_matrix_sync(ah, sQh + wm*136 + d8*16, 136);
                #pragma unroll
                for (int j = 0; j < 2; j++) {
                    wmma::fragment<wmma::matrix_b,16,16,16,__half,wmma::col_major> kh;
                    wmma::load_matrix_sync(kh, sKh + (wn + j*16)*136 + d8*16, 136);
                    wmma::mma_sync(sacc[j], ah, kh, sacc[j]);
                }
            }
            wmma::store_matrix_sync(sS + wm*68 + wn,      sacc[0], 68, wmma::mem_row_major);
            wmma::store_matrix_sync(sS + wm*68 + wn + 16, sacc[1], 68, wmma::mem_row_major);
        }
        __syncthreads();

        // online softmax + fused O rescale (4 threads per row)
        {
            int r    = tid >> 2;
            int lane = tid & 3;
            bool diag = (kt == qt);
            int jmax = diag ? (r + 1) : 64;

            float lm = -INFINITY;
            #pragma unroll
            for (int jj = 0; jj < 16; jj++) {
                int j = lane*16 + jj;
                if (j < jmax) lm = fmaxf(lm, sS[r*68 + j] * scale);
            }
            lm = fmaxf(lm, __shfl_xor_sync(0xffffffffu, lm, 1));
            lm = fmaxf(lm, __shfl_xor_sync(0xffffffffu, lm, 2));
            float mo = smx[r];
            float mn = fmaxf(mo, lm);

            float rl = 0.0f;
            #pragma unroll
            for (int jj = 0; jj < 16; jj++) {
                int j = lane*16 + jj;
                float p = 0.0f;
                if (j < jmax) { p = __expf(sS[r*68 + j] * scale - mn); rl += p; }
                sP[r*72 + j] = __float2half(p);
            }
            rl += __shfl_xor_sync(0xffffffffu, rl, 1);
            rl += __shfl_xor_sync(0xffffffffu, rl, 2);

            float a = __expf(mo - mn);
            if (lane == 0) {
                smx[r] = mn;
                sl[r]  = sl[r] * a + rl;
            }
            #pragma unroll
            for (int dd = 0; dd < 32; dd++)
                sO[r*132 + lane*32 + dd] *= a;
        }
        __syncthreads();

        // O += P @ V
        {
            int wn2 = (wid & 1) * 64;
            wmma::fragment<wmma::accumulator,16,16,16,float> oc[4];
            #pragma unroll
            for (int j = 0; j < 4; j++)
                wmma::load_matrix_sync(oc[j], sO + wm*132 + wn2 + j*16, 132, wmma::mem_row_major);
            #pragma unroll
            for (int kk = 0; kk < 4; kk++) {
                wmma::fragment<wmma::matrix_a,16,16,16,__half,wmma::row_major> pf;
                wmma::load_matrix_sync(pf, sP + wm*72 + kk*16, 72);
                #pragma unroll
                for (int j = 0; j < 4; j++) {
                    wmma::fragment<wmma::matrix_b,16,16,16,__half,wmma::row_major> vf;
                    wmma::load_matrix_sync(vf, sV + (kk*16)*136 + wn2 + j*16, 136);
                    wmma::mma_sync(oc[j], pf, vf, oc[j]);
                }
            }
            #pragma unroll
            for (int j = 0; j < 4; j++)
                wmma::store_matrix_sync(sO + wm*132 + wn2 + j*16, oc[j], 132, wmma::mem_row_major);
        }
        __syncthreads();
    }

    // epilogue: normalize, merge heads, single fp16 output
    for (int v = tid; v < 64*128; v += 256) {
        int r = v >> 7, d = v & 127;
        float o = sO[r*132 + d] / sl[r];
        size_t dst = ((size_t)b * SEQ + q0 + r) * HID + (size_t)h * HDIM + d;
        g_AO[dst] = __float2half(o);
    }
}

// ---------------- launch ----------------
extern "C" void kernel_launch(void* const* d_in, const int* in_sizes, int n_in,
                              void* d_out, int out_size) {
    const float* X    = (const float*)d_in[0];
    const float* Wqkv = (const float*)d_in[1];
    const float* Wo   = (const float*)d_in[2];

    cudaFuncSetAttribute(flash_kernel, cudaFuncAttributeMaxDynamicSharedMemorySize, FL_SMEM);
    cudaFuncSetAttribute(gemm_qkv_merged_kernel, cudaFuncAttributeMaxDynamicSharedMemorySize, GEMM_SMEM);
    cudaFuncSetAttribute(gemm_out_kernel, cudaFuncAttributeMaxDynamicSharedMemorySize, GEMM_SMEM);

    __half *Xhi, *Wqh, *Woh, *AO;
    cudaGetSymbolAddress((void**)&Xhi, g_Xhi);
    cudaGetSymbolAddress((void**)&Wqh, g_Wqkvhi);
    cudaGetSymbolAddress((void**)&Woh, g_Wohi);
    cudaGetSymbolAddress((void**)&AO,  g_AO);

    conv_x_kernel    <<<(MROWS*HID + 255)/256, 256>>>(X);
    conv_wqkv_kernel <<<(QKVN*HID  + 255)/256, 256>>>(Wqkv);
    conv_wo_kernel   <<<(HID*HID   + 255)/256, 256>>>(Wo);
    rope_table_kernel<<<(SEQ*64    + 255)/256, 256>>>();

    // full QKV projection in one launch (M=4096, N=12288), pure fp16
    gemm_qkv_merged_kernel<<<(MROWS/128)*(QKVN/128), 256, GEMM_SMEM>>>(
        Xhi, Wqh, HID, MROWS/128, QKVN/128);

    flash_kernel<<<dim3(SEQ/64, NHEAD, BATCH), 256, FL_SMEM>>>();

    // Output projection (N=4096): pure fp16
    gemm_out_kernel<<<(MROWS/128)*(HID/128), 256, GEMM_SMEM>>>(
        AO, Woh, (float*)d_out, HID, HID, MROWS/128, HID/128);
}

// round 16
// speedup vs baseline: 6.4717x; 1.0356x over previous
#include <cuda_runtime.h>
#include <cuda_fp16.h>
#include <mma.h>
#include <math.h>
#include <stdint.h>

using namespace nvcuda;

#define BATCH 2
#define SEQ   2048
#define HID   4096
#define NHEAD 32
#define HDIM  128
#define MROWS (BATCH*SEQ)     /* 4096 */
#define QKVN  (3*HID)         /* 12288 */

// ---------------- scratch ----------------
__device__ __half g_Xhi   [MROWS*HID];
__device__ __half g_Wqkvhi[QKVN*HID];
__device__ __half g_Wohi  [HID*HID];
__device__ __half g_Qhi   [MROWS*HID];
__device__ __half g_Khi   [MROWS*HID];
__device__ __half g_V     [MROWS*HID];
__device__ __half g_AO    [MROWS*HID];
__device__ float  g_cos   [SEQ*64];
__device__ float  g_sin   [SEQ*64];

// ---------------- cp.async helpers ----------------
static __device__ __forceinline__ uint32_t smem_u32(const void* p) {
    uint32_t a;
    asm("{ .reg .u64 t; cvta.to.shared.u64 t, %1; cvt.u32.u64 %0, t; }" : "=r"(a) : "l"(p));
    return a;
}
static __device__ __forceinline__ void cp_async16(uint32_t dst, const void* src) {
    asm volatile("cp.async.cg.shared.global [%0], [%1], 16;\n" :: "r"(dst), "l"(src));
}
#define CP_COMMIT() asm volatile("cp.async.commit_group;\n" ::: "memory")
#define CP_WAIT1()  asm volatile("cp.async.wait_group 1;\n" ::: "memory")

// ---------------- elementwise kernels ----------------
__global__ void __launch_bounds__(256) conv_x_kernel(const float* __restrict__ src) {
    int idx = blockIdx.x * blockDim.x + threadIdx.x;
    if (idx < MROWS*HID) g_Xhi[idx] = __float2half(src[idx]);
}
__global__ void __launch_bounds__(256) conv_wqkv_kernel(const float* __restrict__ src) {
    int idx = blockIdx.x * blockDim.x + threadIdx.x;
    if (idx < QKVN*HID) g_Wqkvhi[idx] = __float2half(src[idx]);
}
__global__ void __launch_bounds__(256) conv_wo_kernel(const float* __restrict__ src) {
    int idx = blockIdx.x * blockDim.x + threadIdx.x;
    if (idx < HID*HID) g_Wohi[idx] = __float2half(src[idx]);
}

// ---------------- RoPE cos/sin table ----------------
__global__ void __launch_bounds__(256) rope_table_kernel() {
    int idx = blockIdx.x * blockDim.x + threadIdx.x;
    if (idx >= SEQ*64) return;
    int i = idx & 63;
    int s = idx >> 6;
    double inv = pow(10000.0, -((double)(2*i)) / 128.0);
    float invf = (float)inv;
    float ang  = (float)s * invf;
    g_cos[idx] = (float)cos((double)ang);
    g_sin[idx] = (float)sin((double)ang);
}

// =====================================================================
//  Pipelined fp16 GEMM: CTA 128x128, 256 threads, warp 64x32.
//  KC=32, 2-stage cp.async, pure fp16 A·B.  (unchanged from R15)
// =====================================================================

#define KC        32
#define ARR_HALF  (128*40)
#define STAGE_HALF (2*ARR_HALF)
#define STAGE_BYTES (STAGE_HALF*2)
#define GEMM_SMEM (2*STAGE_BYTES + 128*132*4)

static __device__ __forceinline__ void gemm_load_stage(
    uint32_t stage_base, int tid,
    const __half* __restrict__ A, const __half* __restrict__ B,
    int bm, int bn, int K, int k0)
{
    int chunk = tid & 3;
    int r0    = tid >> 2;
    const char* gA = (const char*)(A + (size_t)bm * K + k0) + chunk * 16;
    const char* gB = (const char*)(B + (size_t)bn * K + k0) + chunk * 16;
    #pragma unroll
    for (int u = 0; u < 2; u++) {
        int row = r0 + u * 64;
        uint32_t so = (uint32_t)(row * 80 + chunk * 16);
        cp_async16(stage_base + so,              gA + (size_t)row * K * 2);
        cp_async16(stage_base + 2*ARR_HALF + so, gB + (size_t)row * K * 2);
    }
}

template<int EPI>
static __device__ __forceinline__ void gemm_body(
    __half* smh, uint32_t smem_base, int tid, int wid,
    const __half* __restrict__ A, const __half* __restrict__ B,
    float* __restrict__ C, int K, int ldc, int bm, int bn)
{
    int wm = (wid >> 2) * 64;
    int wn = (wid & 3) * 32;

    wmma::fragment<wmma::accumulator,16,16,16,float> acc[4][2];
    #pragma unroll
    for (int i = 0; i < 4; i++)
        #pragma unroll
        for (int j = 0; j < 2; j++)
            wmma::fill_fragment(acc[i][j], 0.0f);

    const int NIT = K / KC;

    gemm_load_stage(smem_base,               tid, A, B, bm, bn, K, 0);
    CP_COMMIT();
    gemm_load_stage(smem_base + STAGE_BYTES, tid, A, B, bm, bn, K, KC);
    CP_COMMIT();

    for (int it = 0; it < NIT; it++) {
        CP_WAIT1();
        __syncthreads();

        const __half* st = smh + (size_t)(it & 1) * STAGE_HALF;
        const __half* sA = st;
        const __half* sB = st + ARR_HALF;

        #pragma unroll
        for (int kk = 0; kk < 2; kk++) {
            wmma::fragment<wmma::matrix_b,16,16,16,__half,wmma::col_major> bf[2];
            #pragma unroll
            for (int j = 0; j < 2; j++)
                wmma::load_matrix_sync(bf[j], sB + (wn + j*16)*40 + kk*16, 40);
            #pragma unroll
            for (int i = 0; i < 4; i++) {
                wmma::fragment<wmma::matrix_a,16,16,16,__half,wmma::row_major> af;
                wmma::load_matrix_sync(af, sA + (wm + i*16)*40 + kk*16, 40);
                #pragma unroll
                for (int j = 0; j < 2; j++)
                    wmma::mma_sync(acc[i][j], af, bf[j], acc[i][j]);
            }
        }
        __syncthreads();

        int nxt = it + 2;
        if (nxt < NIT)
            gemm_load_stage(smem_base + (uint32_t)(nxt & 1) * STAGE_BYTES, tid,
                            A, B, bm, bn, K, nxt * KC);
        CP_COMMIT();
    }

    if (EPI == 0) {
        #pragma unroll
        for (int i = 0; i < 4; i++)
            #pragma unroll
            for (int j = 0; j < 2; j++) {
                size_t off = (size_t)(bm + wm + i*16) * ldc + bn + wn + j*16;
                wmma::store_matrix_sync(&C[off], acc[i][j], ldc, wmma::mem_row_major);
            }
        return;
    }

    float* sC = (float*)(smh + 2*STAGE_HALF);
    #pragma unroll
    for (int i = 0; i < 4; i++)
        #pragma unroll
        for (int j = 0; j < 2; j++)
            wmma::store_matrix_sync(sC + (wm + i*16)*132 + wn + j*16, acc[i][j],
                                    132, wmma::mem_row_major);
    __syncthreads();

    int h = (bn >> 7) & 31;
    if (EPI == 1) {
        __half* D = (bn >= HID) ? g_Khi : g_Qhi;
        for (int idx = tid; idx < 128*64; idx += 256) {
            int r = idx >> 6, d = idx & 63;
            float x1 = sC[r*132 + d];
            float x2 = sC[r*132 + d + 64];
            int row = bm + r;
            int s   = row & (SEQ-1);
            int b   = row >> 11;
            float c  = g_cos[s*64 + d];
            float sn = g_sin[s*64 + d];
            size_t dst = (((size_t)b * NHEAD + h) * SEQ + s) * HDIM + d;
            D[dst]    = __float2half(x1*c - x2*sn);
            D[dst+64] = __float2half(x1*sn + x2*c);
        }
    } else {
        for (int idx = tid; idx < 128*128; idx += 256) {
            int r = idx >> 7, d = idx & 127;
            int row = bm + r;
            int s   = row & (SEQ-1);
            int b   = row >> 11;
            g_V[(((size_t)b * NHEAD + h) * SEQ + s) * HDIM + d] = __float2half(sC[r*132 + d]);
        }
    }
}

__global__ void __launch_bounds__(256, 2) gemm_qkv_merged_kernel(
    const __half* __restrict__ A, const __half* __restrict__ B,
    int K, int grid_m, int grid_n)
{
    extern __shared__ __half smh[];
    uint32_t smem_base = smem_u32(smh);
    int tid = threadIdx.x;
    int wid = tid >> 5;

    int pid = blockIdx.x;
    const int GRPW = 16;
    int width = GRPW * grid_n;
    int g   = pid / width;
    int rem = pid - g * width;
    int gm  = grid_m - g * GRPW; if (gm > GRPW) gm = GRPW;
    int bm  = (g * GRPW + (rem % gm)) * 128;
    int bn  = (rem / gm) * 128;

    if (bn < 2*HID)
        gemm_body<1>(smh, smem_base, tid, wid, A, B, nullptr, K, 0, bm, bn);
    else
        gemm_body<2>(smh, smem_base, tid, wid, A, B, nullptr, K, 0, bm, bn);
}

__global__ void __launch_bounds__(256, 2) gemm_out_kernel(
    const __half* __restrict__ A, const __half* __restrict__ B,
    float* __restrict__ C, int K, int ldc, int grid_m, int grid_n)
{
    extern __shared__ __half smh[];
    uint32_t smem_base = smem_u32(smh);
    int tid = threadIdx.x;
    int wid = tid >> 5;

    int pid = blockIdx.x;
    const int GRPW = 16;
    int width = GRPW * grid_n;
    int g   = pid / width;
    int rem = pid - g * width;
    int gm  = grid_m - g * GRPW; if (gm > GRPW) gm = GRPW;
    int bm  = (g * GRPW + (rem % gm)) * 128;
    int bn  = (rem / gm) * 128;

    gemm_body<0>(smh, smem_base, tid, wid, A, B, C, K, ldc, bm, bn);
}

// ---------------- flash attention: 128-row q tiles, 512 threads ----------------
// smem: Q 128x136h ; 2 x (K 64x136h, V 64x136h) ; S 128x68f ; P 128x72h ;
//       O 128x132f ; m/l 2x128f  => 226304 B
#define KTILE_H  (64*136)
#define KTILE_B  (KTILE_H*2)
#define FL_SMEM  (128*136*2 + 4*KTILE_B/2*2 + 128*68*4 + 128*72*2 + 128*132*4 + 2*128*4)

static __device__ __forceinline__ void flash_issue_tile(
    uint32_t dKh, uint32_t dV,
    const __half* __restrict__ Kh, const __half* __restrict__ V, int tid)
{
    int chunk = tid & 15;
    int r0    = tid >> 4;   // 0..31
    #pragma unroll
    for (int u = 0; u < 2; u++) {
        int r = r0 + u * 32;
        uint32_t so = (uint32_t)(r * 272 + chunk * 16);
        size_t   go = (size_t)r * HDIM * 2 + chunk * 16;
        cp_async16(dKh + so, (const char*)Kh + go);
        cp_async16(dV  + so, (const char*)V  + go);
    }
}

__global__ void __launch_bounds__(512) flash_kernel() {
    extern __shared__ unsigned char smraw[];
    __half* sQh = (__half*)smraw;                  // 128*136
    __half* sKB = sQh + 128*136;                   // 2 buffers x (Kh, V) 64*136 each
    float*  sS  = (float*)(sKB + 4*KTILE_H);       // 128*68
    __half* sP  = (__half*)(sS + 128*68);          // 128*72
    float*  sO  = (float*)(sP + 128*72);           // 128*132
    float*  smx = sO + 128*132;
    float*  sl  = smx + 128;

    int tid = threadIdx.x;
    int wid = tid >> 5;
    int qt  = gridDim.x - 1 - blockIdx.x;   // longest CTAs first
    int h   = blockIdx.y;
    int b   = blockIdx.z;
    int bh  = b * NHEAD + h;
    int q0  = qt * 128;

    const float scale = 0.08838834764831845f;

    const __half* Khg = g_Khi + (size_t)bh * SEQ * HDIM;
    const __half* Vg  = g_V   + (size_t)bh * SEQ * HDIM;

    uint32_t sKB_u = smem_u32(sKB);

    flash_issue_tile(sKB_u, sKB_u + KTILE_B, Khg, Vg, tid);
    CP_COMMIT();

    {
        const __half* Qh = g_Qhi + ((size_t)bh * SEQ + q0) * HDIM;
        for (int v = tid; v < 2048; v += 512) {
            int r = v >> 4, c = (v & 15) << 3;
            *(int4*)(sQh + r*136 + c) = *(const int4*)(Qh + r*HDIM + c);
        }
    }
    for (int v = tid; v < 128*132; v += 512) sO[v] = 0.0f;
    if (tid < 128) { smx[tid] = -INFINITY; sl[tid] = 0.0f; }

    int ktmax = qt * 2 + 1;     // last k tile index (covers q0..q0+127)

    for (int kt = 0; kt <= ktmax; kt++) {
        if (kt + 1 <= ktmax) {
            uint32_t nb = sKB_u + (uint32_t)((kt + 1) & 1) * 2 * KTILE_B;
            flash_issue_tile(nb, nb + KTILE_B,
                             Khg + (size_t)(kt+1)*64*HDIM,
                             Vg  + (size_t)(kt+1)*64*HDIM, tid);
        }
        CP_COMMIT();
        CP_WAIT1();
        __syncthreads();

        __half* sKh = sKB + (size_t)(kt & 1) * 2 * KTILE_H;
        __half* sV  = sKh + KTILE_H;

        // S = Q K^T : 128x64, 16 warps as 8x2 grid of 16x32 tiles
        {
            int wms = (wid >> 1) * 16;
            int wns = (wid & 1) * 32;
            wmma::fragment<wmma::accumulator,16,16,16,float> sacc[2];
            wmma::fill_fragment(sacc[0], 0.0f);
            wmma::fill_fragment(sacc[1], 0.0f);
            #pragma unroll
            for (int d8 = 0; d8 < 8; d8++) {
                wmma::fragment<wmma::matrix_a,16,16,16,__half,wmma::row_major> ah;
                wmma::load_matrix_sync(ah, sQh + wms*136 + d8*16, 136);
                #pragma unroll
                for (int j = 0; j < 2; j++) {
                    wmma::fragment<wmma::matrix_b,16,16,16,__half,wmma::col_major> kh;
                    wmma::load_matrix_sync(kh, sKh + (wns + j*16)*136 + d8*16, 136);
                    wmma::mma_sync(sacc[j], ah, kh, sacc[j]);
                }
            }
            wmma::store_matrix_sync(sS + wms*68 + wns,      sacc[0], 68, wmma::mem_row_major);
            wmma::store_matrix_sync(sS + wms*68 + wns + 16, sacc[1], 68, wmma::mem_row_major);
        }
        __syncthreads();

        // online softmax + fused O rescale (4 threads per row, 128 rows)
        {
            int r    = tid >> 2;
            int lane = tid & 3;
            int k0   = kt * 64;
            int jm   = q0 + r + 1 - k0;
            int jmax = jm < 0 ? 0 : (jm > 64 ? 64 : jm);

            float lm = -INFINITY;
            #pragma unroll
            for (int jj = 0; jj < 16; jj++) {
                int j = lane*16 + jj;
                if (j < jmax) lm = fmaxf(lm, sS[r*68 + j] * scale);
            }
            lm = fmaxf(lm, __shfl_xor_sync(0xffffffffu, lm, 1));
            lm = fmaxf(lm, __shfl_xor_sync(0xffffffffu, lm, 2));
            float mo = smx[r];
            float mn = fmaxf(mo, lm);

            float rl = 0.0f;
            #pragma unroll
            for (int jj = 0; jj < 16; jj++) {
                int j = lane*16 + jj;
                float p = 0.0f;
                if (j < jmax) { p = __expf(sS[r*68 + j] * scale - mn); rl += p; }
                sP[r*72 + j] = __float2half(p);
            }
            rl += __shfl_xor_sync(0xffffffffu, rl, 1);
            rl += __shfl_xor_sync(0xffffffffu, rl, 2);

            float a = __expf(mo - mn);
            if (lane == 0) {
                smx[r] = mn;
                sl[r]  = sl[r] * a + rl;
            }
            #pragma unroll
            for (int dd = 0; dd < 32; dd++)
                sO[r*132 + lane*32 + dd] *= a;
        }
        __syncthreads();

        // O += P @ V : 128x128, 16 warps as 4x4 grid of 32x32 tiles
        {
            int wmo = (wid >> 2) * 32;
            int wno = (wid & 3) * 32;
            wmma::fragment<wmma::accumulator,16,16,16,float> oc[2][2];
            #pragma unroll
            for (int i = 0; i < 2; i++)
                #pragma unroll
                for (int j = 0; j < 2; j++)
                    wmma::load_matrix_sync(oc[i][j], sO + (wmo + i*16)*132 + wno + j*16,
                                           132, wmma::mem_row_major);
            #pragma unroll
            for (int kk = 0; kk < 4; kk++) {
                wmma::fragment<wmma::matrix_a,16,16,16,__half,wmma::row_major> pf[2];
                #pragma unroll
                for (int i = 0; i < 2; i++)
                    wmma::load_matrix_sync(pf[i], sP + (wmo + i*16)*72 + kk*16, 72);
                #pragma unroll
                for (int j = 0; j < 2; j++) {
                    wmma::fragment<wmma::matrix_b,16,16,16,__half,wmma::row_major> vf;
                    wmma::load_matrix_sync(vf, sV + (kk*16)*136 + wno + j*16, 136);
                    #pragma unroll
                    for (int i = 0; i < 2; i++)
                        wmma::mma_sync(oc[i][j], pf[i], vf, oc[i][j]);
                }
            }
            #pragma unroll
            for (int i = 0; i < 2; i++)
                #pragma unroll
                for (int j = 0; j < 2; j++)
                    wmma::store_matrix_sync(sO + (wmo + i*16)*132 + wno + j*16, oc[i][j],
                                            132, wmma::mem_row_major);
        }
        __syncthreads();
    }

    // epilogue: normalize, merge heads, single fp16 output
    for (int v = tid; v < 128*128; v += 512) {
        int r = v >> 7, d = v & 127;
        float o = sO[r*132 + d] / sl[r];
        size_t dst = ((size_t)b * SEQ + q0 + r) * HID + (size_t)h * HDIM + d;
        g_AO[dst] = __float2half(o);
    }
}

// ---------------- launch ----------------
extern "C" void kernel_launch(void* const* d_in, const int* in_sizes, int n_in,
                              void* d_out, int out_size) {
    const float* X    = (const float*)d_in[0];
    const float* Wqkv = (const float*)d_in[1];
    const float* Wo   = (const float*)d_in[2];

    cudaFuncSetAttribute(flash_kernel, cudaFuncAttributeMaxDynamicSharedMemorySize, FL_SMEM);
    cudaFuncSetAttribute(gemm_qkv_merged_kernel, cudaFuncAttributeMaxDynamicSharedMemorySize, GEMM_SMEM);
    cudaFuncSetAttribute(gemm_out_kernel, cudaFuncAttributeMaxDynamicSharedMemorySize, GEMM_SMEM);

    __half *Xhi, *Wqh, *Woh, *AO;
    cudaGetSymbolAddress((void**)&Xhi, g_Xhi);
    cudaGetSymbolAddress((void**)&Wqh, g_Wqkvhi);
    cudaGetSymbolAddress((void**)&Woh, g_Wohi);
    cudaGetSymbolAddress((void**)&AO,  g_AO);

    conv_x_kernel    <<<(MROWS*HID + 255)/256, 256>>>(X);
    conv_wqkv_kernel <<<(QKVN*HID  + 255)/256, 256>>>(Wqkv);
    conv_wo_kernel   <<<(HID*HID   + 255)/256, 256>>>(Wo);
    rope_table_kernel<<<(SEQ*64    + 255)/256, 256>>>();

    // full QKV projection in one launch (M=4096, N=12288), pure fp16
    gemm_qkv_merged_kernel<<<(MROWS/128)*(QKVN/128), 256, GEMM_SMEM>>>(
        Xhi, Wqh, HID, MROWS/128, QKVN/128);

    flash_kernel<<<dim3(SEQ/128, NHEAD, BATCH), 512, FL_SMEM>>>();

    // Output projection (N=4096): pure fp16
    gemm_out_kernel<<<(MROWS/128)*(HID/128), 256, GEMM_SMEM>>>(
        AO, Woh, (float*)d_out, HID, HID, MROWS/128, HID/128);
}

// round 17
// speedup vs baseline: 6.9580x; 1.0752x over previous
#include <cuda_runtime.h>
#include <cuda_fp16.h>
#include <mma.h>
#include <math.h>
#include <stdint.h>

using namespace nvcuda;

#define BATCH 2
#define SEQ   2048
#define HID   4096
#define NHEAD 32
#define HDIM  128
#define MROWS (BATCH*SEQ)     /* 4096 */
#define QKVN  (3*HID)         /* 12288 */

// ---------------- scratch ----------------
__device__ __half g_Xhi   [MROWS*HID];
__device__ __half g_Wqkvhi[QKVN*HID];
__device__ __half g_Wohi  [HID*HID];
__device__ __half g_Qhi   [MROWS*HID];
__device__ __half g_Khi   [MROWS*HID];
__device__ __half g_V     [MROWS*HID];
__device__ __half g_AO    [MROWS*HID];
__device__ float  g_cos   [SEQ*64];
__device__ float  g_sin   [SEQ*64];

// ---------------- cp.async helpers ----------------
static __device__ __forceinline__ uint32_t smem_u32(const void* p) {
    uint32_t a;
    asm("{ .reg .u64 t; cvta.to.shared.u64 t, %1; cvt.u32.u64 %0, t; }" : "=r"(a) : "l"(p));
    return a;
}
static __device__ __forceinline__ void cp_async16(uint32_t dst, const void* src) {
    asm volatile("cp.async.cg.shared.global [%0], [%1], 16;\n" :: "r"(dst), "l"(src));
}
#define CP_COMMIT() asm volatile("cp.async.commit_group;\n" ::: "memory")
#define CP_WAIT1()  asm volatile("cp.async.wait_group 1;\n" ::: "memory")

// ---------------- elementwise kernels ----------------
__global__ void __launch_bounds__(256) conv_x_kernel(const float* __restrict__ src) {
    int idx = blockIdx.x * blockDim.x + threadIdx.x;
    if (idx < MROWS*HID) g_Xhi[idx] = __float2half(src[idx]);
}
__global__ void __launch_bounds__(256) conv_wqkv_kernel(const float* __restrict__ src) {
    int idx = blockIdx.x * blockDim.x + threadIdx.x;
    if (idx < QKVN*HID) g_Wqkvhi[idx] = __float2half(src[idx]);
}
__global__ void __launch_bounds__(256) conv_wo_kernel(const float* __restrict__ src) {
    int idx = blockIdx.x * blockDim.x + threadIdx.x;
    if (idx < HID*HID) g_Wohi[idx] = __float2half(src[idx]);
}

// ---------------- RoPE cos/sin table ----------------
__global__ void __launch_bounds__(256) rope_table_kernel() {
    int idx = blockIdx.x * blockDim.x + threadIdx.x;
    if (idx >= SEQ*64) return;
    int i = idx & 63;
    int s = idx >> 6;
    double inv = pow(10000.0, -((double)(2*i)) / 128.0);
    float invf = (float)inv;
    float ang  = (float)s * invf;
    g_cos[idx] = (float)cos((double)ang);
    g_sin[idx] = (float)sin((double)ang);
}

// =====================================================================
//  Pipelined fp16 GEMM: CTA 128x128, 256 threads, warp 64x32.
//  KC=64 (halved barrier count), 2-stage cp.async, pure fp16 A·B.
//  Epilogue C-tile overlays the dead stage buffers -> 73.7KB, 2 CTAs/SM.
// =====================================================================

#define KC        64
#define ARR_HALF  (128*72)                 /* 64 data halves + 8 pad */
#define STAGE_HALF (2*ARR_HALF)            /* 18432: A + B */
#define STAGE_BYTES (STAGE_HALF*2)         /* 36864 */
#define GEMM_SMEM (2*STAGE_BYTES)          /* 73728; C tile (67584) overlays */

static __device__ __forceinline__ void gemm_load_stage(
    uint32_t stage_base, int tid,
    const __half* __restrict__ A, const __half* __restrict__ B,
    int bm, int bn, int K, int k0)
{
    int chunk = tid & 7;        // 16B chunk within 128B data row
    int r0    = tid >> 3;       // 0..31
    const char* gA = (const char*)(A + (size_t)bm * K + k0) + chunk * 16;
    const char* gB = (const char*)(B + (size_t)bn * K + k0) + chunk * 16;
    #pragma unroll
    for (int u = 0; u < 4; u++) {
        int row = r0 + u * 32;
        uint32_t so = (uint32_t)(row * 144 + chunk * 16);
        cp_async16(stage_base + so,              gA + (size_t)row * K * 2);
        cp_async16(stage_base + 2*ARR_HALF + so, gB + (size_t)row * K * 2);
    }
}

template<int EPI>
static __device__ __forceinline__ void gemm_body(
    __half* smh, uint32_t smem_base, int tid, int wid,
    const __half* __restrict__ A, const __half* __restrict__ B,
    float* __restrict__ C, int K, int ldc, int bm, int bn)
{
    int wm = (wid >> 2) * 64;
    int wn = (wid & 3) * 32;

    wmma::fragment<wmma::accumulator,16,16,16,float> acc[4][2];
    #pragma unroll
    for (int i = 0; i < 4; i++)
        #pragma unroll
        for (int j = 0; j < 2; j++)
            wmma::fill_fragment(acc[i][j], 0.0f);

    const int NIT = K / KC;

    gemm_load_stage(smem_base,               tid, A, B, bm, bn, K, 0);
    CP_COMMIT();
    gemm_load_stage(smem_base + STAGE_BYTES, tid, A, B, bm, bn, K, KC);
    CP_COMMIT();

    for (int it = 0; it < NIT; it++) {
        CP_WAIT1();
        __syncthreads();

        const __half* st = smh + (size_t)(it & 1) * STAGE_HALF;
        const __half* sA = st;
        const __half* sB = st + ARR_HALF;

        #pragma unroll
        for (int kk = 0; kk < 4; kk++) {
            wmma::fragment<wmma::matrix_b,16,16,16,__half,wmma::col_major> bf[2];
            #pragma unroll
            for (int j = 0; j < 2; j++)
                wmma::load_matrix_sync(bf[j], sB + (wn + j*16)*72 + kk*16, 72);
            #pragma unroll
            for (int i = 0; i < 4; i++) {
                wmma::fragment<wmma::matrix_a,16,16,16,__half,wmma::row_major> af;
                wmma::load_matrix_sync(af, sA + (wm + i*16)*72 + kk*16, 72);
                #pragma unroll
                for (int j = 0; j < 2; j++)
                    wmma::mma_sync(acc[i][j], af, bf[j], acc[i][j]);
            }
        }
        __syncthreads();

        int nxt = it + 2;
        if (nxt < NIT)
            gemm_load_stage(smem_base + (uint32_t)(nxt & 1) * STAGE_BYTES, tid,
                            A, B, bm, bn, K, nxt * KC);
        CP_COMMIT();
    }

    if (EPI == 0) {
        #pragma unroll
        for (int i = 0; i < 4; i++)
            #pragma unroll
            for (int j = 0; j < 2; j++) {
                size_t off = (size_t)(bm + wm + i*16) * ldc + bn + wn + j*16;
                wmma::store_matrix_sync(&C[off], acc[i][j], ldc, wmma::mem_row_major);
            }
        return;
    }

    // stage C tile (128 x 128, stride 132) overlaying the dead stage buffers
    float* sC = (float*)smh;
    #pragma unroll
    for (int i = 0; i < 4; i++)
        #pragma unroll
        for (int j = 0; j < 2; j++)
            wmma::store_matrix_sync(sC + (wm + i*16)*132 + wn + j*16, acc[i][j],
                                    132, wmma::mem_row_major);
    __syncthreads();

    int h = (bn >> 7) & 31;
    if (EPI == 1) {
        __half* D = (bn >= HID) ? g_Khi : g_Qhi;
        for (int idx = tid; idx < 128*64; idx += 256) {
            int r = idx >> 6, d = idx & 63;
            float x1 = sC[r*132 + d];
            float x2 = sC[r*132 + d + 64];
            int row = bm + r;
            int s   = row & (SEQ-1);
            int b   = row >> 11;
            float c  = g_cos[s*64 + d];
            float sn = g_sin[s*64 + d];
            size_t dst = (((size_t)b * NHEAD + h) * SEQ + s) * HDIM + d;
            D[dst]    = __float2half(x1*c - x2*sn);
            D[dst+64] = __float2half(x1*sn + x2*c);
        }
    } else {
        for (int idx = tid; idx < 128*128; idx += 256) {
            int r = idx >> 7, d = idx & 127;
            int row = bm + r;
            int s   = row & (SEQ-1);
            int b   = row >> 11;
            g_V[(((size_t)b * NHEAD + h) * SEQ + s) * HDIM + d] = __float2half(sC[r*132 + d]);
        }
    }
}

__global__ void __launch_bounds__(256, 2) gemm_qkv_merged_kernel(
    const __half* __restrict__ A, const __half* __restrict__ B,
    int K, int grid_m, int grid_n)
{
    extern __shared__ __half smh[];
    uint32_t smem_base = smem_u32(smh);
    int tid = threadIdx.x;
    int wid = tid >> 5;

    int pid = blockIdx.x;
    const int GRPW = 16;
    int width = GRPW * grid_n;
    int g   = pid / width;
    int rem = pid - g * width;
    int gm  = grid_m - g * GRPW; if (gm > GRPW) gm = GRPW;
    int bm  = (g * GRPW + (rem % gm)) * 128;
    int bn  = (rem / gm) * 128;

    if (bn < 2*HID)
        gemm_body<1>(smh, smem_base, tid, wid, A, B, nullptr, K, 0, bm, bn);
    else
        gemm_body<2>(smh, smem_base, tid, wid, A, B, nullptr, K, 0, bm, bn);
}

__global__ void __launch_bounds__(256, 2) gemm_out_kernel(
    const __half* __restrict__ A, const __half* __restrict__ B,
    float* __restrict__ C, int K, int ldc, int grid_m, int grid_n)
{
    extern __shared__ __half smh[];
    uint32_t smem_base = smem_u32(smh);
    int tid = threadIdx.x;
    int wid = tid >> 5;

    int pid = blockIdx.x;
    const int GRPW = 16;
    int width = GRPW * grid_n;
    int g   = pid / width;
    int rem = pid - g * width;
    int gm  = grid_m - g * GRPW; if (gm > GRPW) gm = GRPW;
    int bm  = (g * GRPW + (rem % gm)) * 128;
    int bn  = (rem / gm) * 128;

    gemm_body<0>(smh, smem_base, tid, wid, A, B, C, K, ldc, bm, bn);
}

// ---------------- flash attention: 128-row q tiles, 512 threads (unchanged R16) ----------------
#define KTILE_H  (64*136)
#define KTILE_B  (KTILE_H*2)
#define FL_SMEM  (128*136*2 + 4*KTILE_B/2*2 + 128*68*4 + 128*72*2 + 128*132*4 + 2*128*4)

static __device__ __forceinline__ void flash_issue_tile(
    uint32_t dKh, uint32_t dV,
    const __half* __restrict__ Kh, const __half* __restrict__ V, int tid)
{
    int chunk = tid & 15;
    int r0    = tid >> 4;   // 0..31
    #pragma unroll
    for (int u = 0; u < 2; u++) {
        int r = r0 + u * 32;
        uint32_t so = (uint32_t)(r * 272 + chunk * 16);
        size_t   go = (size_t)r * HDIM * 2 + chunk * 16;
        cp_async16(dKh + so, (const char*)Kh + go);
        cp_async16(dV  + so, (const char*)V  + go);
    }
}

__global__ void __launch_bounds__(512) flash_kernel() {
    extern __shared__ unsigned char smraw[];
    __half* sQh = (__half*)smraw;
    __half* sKB = sQh + 128*136;
    float*  sS  = (float*)(sKB + 4*KTILE_H);
    __half* sP  = (__half*)(sS + 128*68);
    float*  sO  = (float*)(sP + 128*72);
    float*  smx = sO + 128*132;
    float*  sl  = smx + 128;

    int tid = threadIdx.x;
    int wid = tid >> 5;
    int qt  = gridDim.x - 1 - blockIdx.x;
    int h   = blockIdx.y;
    int b   = blockIdx.z;
    int bh  = b * NHEAD + h;
    int q0  = qt * 128;

    const float scale = 0.08838834764831845f;

    const __half* Khg = g_Khi + (size_t)bh * SEQ * HDIM;
    const __half* Vg  = g_V   + (size_t)bh * SEQ * HDIM;

    uint32_t sKB_u = smem_u32(sKB);

    flash_issue_tile(sKB_u, sKB_u + KTILE_B, Khg, Vg, tid);
    CP_COMMIT();

    {
        const __half* Qh = g_Qhi + ((size_t)bh * SEQ + q0) * HDIM;
        for (int v = tid; v < 2048; v += 512) {
            int r = v >> 4, c = (v & 15) << 3;
            *(int4*)(sQh + r*136 + c) = *(const int4*)(Qh + r*HDIM + c);
        }
    }
    for (int v = tid; v < 128*132; v += 512) sO[v] = 0.0f;
    if (tid < 128) { smx[tid] = -INFINITY; sl[tid] = 0.0f; }

    int ktmax = qt * 2 + 1;

    for (int kt = 0; kt <= ktmax; kt++) {
        if (kt + 1 <= ktmax) {
            uint32_t nb = sKB_u + (uint32_t)((kt + 1) & 1) * 2 * KTILE_B;
            flash_issue_tile(nb, nb + KTILE_B,
                             Khg + (size_t)(kt+1)*64*HDIM,
                             Vg  + (size_t)(kt+1)*64*HDIM, tid);
        }
        CP_COMMIT();
        CP_WAIT1();
        __syncthreads();

        __half* sKh = sKB + (size_t)(kt & 1) * 2 * KTILE_H;
        __half* sV  = sKh + KTILE_H;

        // S = Q K^T : 128x64, 16 warps as 8x2 grid of 16x32 tiles
        {
            int wms = (wid >> 1) * 16;
            int wns = (wid & 1) * 32;
            wmma::fragment<wmma::accumulator,16,16,16,float> sacc[2];
            wmma::fill_fragment(sacc[0], 0.0f);
            wmma::fill_fragment(sacc[1], 0.0f);
            #pragma unroll
            for (int d8 = 0; d8 < 8; d8++) {
                wmma::fragment<wmma::matrix_a,16,16,16,__half,wmma::row_major> ah;
                wmma::load_matrix_sync(ah, sQh + wms*136 + d8*16, 136);
                #pragma unroll
                for (int j = 0; j < 2; j++) {
                    wmma::fragment<wmma::matrix_b,16,16,16,__half,wmma::col_major> kh;
                    wmma::load_matrix_sync(kh, sKh + (wns + j*16)*136 + d8*16, 136);
                    wmma::mma_sync(sacc[j], ah, kh, sacc[j]);
                }
            }
            wmma::store_matrix_sync(sS + wms*68 + wns,      sacc[0], 68, wmma::mem_row_major);
            wmma::store_matrix_sync(sS + wms*68 + wns + 16, sacc[1], 68, wmma::mem_row_major);
        }
        __syncthreads();

        // online softmax + fused O rescale (4 threads per row, 128 rows)
        {
            int r    = tid >> 2;
            int lane = tid & 3;
            int k0   = kt * 64;
            int jm   = q0 + r + 1 - k0;
            int jmax = jm < 0 ? 0 : (jm > 64 ? 64 : jm);

            float lm = -INFINITY;
            #pragma unroll
            for (int jj = 0; jj < 16; jj++) {
                int j = lane*16 + jj;
                if (j < jmax) lm = fmaxf(lm, sS[r*68 + j] * scale);
            }
            lm = fmaxf(lm, __shfl_xor_sync(0xffffffffu, lm, 1));
            lm = fmaxf(lm, __shfl_xor_sync(0xffffffffu, lm, 2));
            float mo = smx[r];
            float mn = fmaxf(mo, lm);

            float rl = 0.0f;
            #pragma unroll
            for (int jj = 0; jj < 16; jj++) {
                int j = lane*16 + jj;
                float p = 0.0f;
                if (j < jmax) { p = __expf(sS[r*68 + j] * scale - mn); rl += p; }
                sP[r*72 + j] = __float2half(p);
            }
            rl += __shfl_xor_sync(0xffffffffu, rl, 1);
            rl += __shfl_xor_sync(0xffffffffu, rl, 2);

            float a = __expf(mo - mn);
            if (lane == 0) {
                smx[r] = mn;
                sl[r]  = sl[r] * a + rl;
            }
            #pragma unroll
            for (int dd = 0; dd < 32; dd++)
                sO[r*132 + lane*32 + dd] *= a;
        }
        __syncthreads();

        // O += P @ V : 128x128, 16 warps as 4x4 grid of 32x32 tiles
        {
            int wmo = (wid >> 2) * 32;
            int wno = (wid & 3) * 32;
            wmma::fragment<wmma::accumulator,16,16,16,float> oc[2][2];
            #pragma unroll
            for (int i = 0; i < 2; i++)
                #pragma unroll
                for (int j = 0; j < 2; j++)
                    wmma::load_matrix_sync(oc[i][j], sO + (wmo + i*16)*132 + wno + j*16,
                                           132, wmma::mem_row_major);
            #pragma unroll
            for (int kk = 0; kk < 4; kk++) {
                wmma::fragment<wmma::matrix_a,16,16,16,__half,wmma::row_major> pf[2];
                #pragma unroll
                for (int i = 0; i < 2; i++)
                    wmma::load_matrix_sync(pf[i], sP + (wmo + i*16)*72 + kk*16, 72);
                #pragma unroll
                for (int j = 0; j < 2; j++) {
                    wmma::fragment<wmma::matrix_b,16,16,16,__half,wmma::row_major> vf;
                    wmma::load_matrix_sync(vf, sV + (kk*16)*136 + wno + j*16, 136);
                    #pragma unroll
                    for (int i = 0; i < 2; i++)
                        wmma::mma_sync(oc[i][j], pf[i], vf, oc[i][j]);
                }
            }
            #pragma unroll
            for (int i = 0; i < 2; i++)
                #pragma unroll
                for (int j = 0; j < 2; j++)
                    wmma::store_matrix_sync(sO + (wmo + i*16)*132 + wno + j*16, oc[i][j],
                                            132, wmma::mem_row_major);
        }
        __syncthreads();
    }

    // epilogue: normalize, merge heads, single fp16 output
    for (int v = tid; v < 128*128; v += 512) {
        int r = v >> 7, d = v & 127;
        float o = sO[r*132 + d] / sl[r];
        size_t dst = ((size_t)b * SEQ + q0 + r) * HID + (size_t)h * HDIM + d;
        g_AO[dst] = __float2half(o);
    }
}

// ---------------- launch ----------------
extern "C" void kernel_launch(void* const* d_in, const int* in_sizes, int n_in,
                              void* d_out, int out_size) {
    const float* X    = (const float*)d_in[0];
    const float* Wqkv = (const float*)d_in[1];
    const float* Wo   = (const float*)d_in[2];

    cudaFuncSetAttribute(flash_kernel, cudaFuncAttributeMaxDynamicSharedMemorySize, FL_SMEM);
    cudaFuncSetAttribute(gemm_qkv_merged_kernel, cudaFuncAttributeMaxDynamicSharedMemorySize, GEMM_SMEM);
    cudaFuncSetAttribute(gemm_out_kernel, cudaFuncAttributeMaxDynamicSharedMemorySize, GEMM_SMEM);

    __half *Xhi, *Wqh, *Woh, *AO;
    cudaGetSymbolAddress((void**)&Xhi, g_Xhi);
    cudaGetSymbolAddress((void**)&Wqh, g_Wqkvhi);
    cudaGetSymbolAddress((void**)&Woh, g_Wohi);
    cudaGetSymbolAddress((void**)&AO,  g_AO);

    conv_x_kernel    <<<(MROWS*HID + 255)/256, 256>>>(X);
    conv_wqkv_kernel <<<(QKVN*HID  + 255)/256, 256>>>(Wqkv);
    conv_wo_kernel   <<<(HID*HID   + 255)/256, 256>>>(Wo);
    rope_table_kernel<<<(SEQ*64    + 255)/256, 256>>>();

    // full QKV projection in one launch (M=4096, N=12288), pure fp16
    gemm_qkv_merged_kernel<<<(MROWS/128)*(QKVN/128), 256, GEMM_SMEM>>>(
        Xhi, Wqh, HID, MROWS/128, QKVN/128);

    flash_kernel<<<dim3(SEQ/128, NHEAD, BATCH), 512, FL_SMEM>>>();

    // Output projection (N=4096): pure fp16
    gemm_out_kernel<<<(MROWS/128)*(HID/128), 256, GEMM_SMEM>>>(
        AO, Woh, (float*)d_out, HID, HID, MROWS/128, HID/128);
}